// round 12
// baseline (speedup 1.0000x reference)
#include <cuda_runtime.h>
#include <math.h>

#define C    128
#define C2   256
#define MAXN 50000
#define MAXE 600000
#define PADMAX 65536
#define SCHUNK 2048
#define TPB  256

// ------------------------------------------------------------------ scratch
__device__ float g_score[MAXN];
__device__ unsigned long long g_keys[PADMAX];
__device__ int   g_permbuf[MAXN];            // concat of per-level perms
__device__ float g_xs1[25088 * C];           // residual after down level 0
__device__ float g_xs2[12544 * C];           // residual after down level 1
__device__ float g_xpool[25088 * C];
__device__ float g_agg[MAXN * C2];
__device__ float g_feat[MAXN * C2];
__device__ float g_h1[MAXN * C];
__device__ float g_h2[MAXN * C];
__device__ float g_xd3[6272 * C];
__device__ float g_xu0[12544 * C];
__device__ float g_xu1[25088 * C];
__device__ int g_nmap[MAXN + 1];
__device__ int g_es[3 * MAXE];
__device__ int g_er[3 * MAXE];
__device__ int g_ecnt[4];
__device__ int g_col[4 * 2 * MAXE];
__device__ int g_rowptr[4 * (MAXN + 2)];
__device__ int g_deg[MAXN + 1];
__device__ int g_cursor[MAXN + 1];

// ------------------------------------------------------------------ helpers
__device__ __forceinline__ float warp_sum(float v) {
    #pragma unroll
    for (int o = 16; o; o >>= 1) v += __shfl_xor_sync(0xffffffffu, v, o);
    return v;
}

__device__ __forceinline__ float gelu_exact(float v) {
    return 0.5f * v * (1.0f + erff(v * 0.70710678118654752f));
}

// ------------------------------------------------------------------ scoring
__global__ void k_score(const float* __restrict__ x, const float* __restrict__ w, int nn) {
    int wid  = (blockIdx.x * blockDim.x + threadIdx.x) >> 5;
    int lane = threadIdx.x & 31;
    if (wid >= nn) return;
    float4 wv = *(const float4*)(w + lane * 4);
    float4 xv = *(const float4*)(x + (size_t)wid * C + lane * 4);
    float dot = xv.x * wv.x + xv.y * wv.y + xv.z * wv.z + xv.w * wv.w;
    float nrm = wv.x * wv.x + wv.y * wv.y + wv.z * wv.z + wv.w * wv.w;
    dot = warp_sum(dot);
    nrm = warp_sum(nrm);
    if (lane == 0) g_score[wid] = tanhf(dot / sqrtf(nrm));
}

// ------------------------------------------------------------------ top-k sort
__global__ void k_keyinit(int nn, int P) {
    int i = blockIdx.x * blockDim.x + threadIdx.x;
    if (i >= P) return;
    unsigned long long kk;
    if (i < nn) {
        unsigned u = __float_as_uint(g_score[i]);
        u = (u & 0x80000000u) ? ~u : (u | 0x80000000u);   // ascending order map
        kk = (((unsigned long long)(~u)) << 32) | (unsigned)i;  // descending score, asc index
    } else {
        kk = 0xFFFFFFFFFFFFFFFFULL;
    }
    g_keys[i] = kk;
}

__global__ void k_sort_local_full() {
    __shared__ unsigned long long sk[SCHUNK];
    int base = blockIdx.x * SCHUNK;
    int t = threadIdx.x;
    sk[t] = g_keys[base + t];
    sk[t + 1024] = g_keys[base + t + 1024];
    __syncthreads();
    for (int k = 2; k <= SCHUNK; k <<= 1) {
        for (int j = k >> 1; j > 0; j >>= 1) {
            int i = ((t & ~(j - 1)) << 1) | (t & (j - 1));
            int l = i | j;
            bool up = (((base + i) & k) == 0);
            unsigned long long a = sk[i], b = sk[l];
            if ((a > b) == up) { sk[i] = b; sk[l] = a; }
            __syncthreads();
        }
    }
    g_keys[base + t] = sk[t];
    g_keys[base + t + 1024] = sk[t + 1024];
}

__global__ void k_sort_global(int j, int k, int P) {
    int t = blockIdx.x * blockDim.x + threadIdx.x;
    if (t >= (P >> 1)) return;
    int i = ((t & ~(j - 1)) << 1) | (t & (j - 1));
    int l = i | j;
    bool up = ((i & k) == 0);
    unsigned long long a = g_keys[i], b = g_keys[l];
    if ((a > b) == up) { g_keys[i] = b; g_keys[l] = a; }
}

__global__ void k_sort_local_merge(int k) {
    __shared__ unsigned long long sk[SCHUNK];
    int base = blockIdx.x * SCHUNK;
    int t = threadIdx.x;
    sk[t] = g_keys[base + t];
    sk[t + 1024] = g_keys[base + t + 1024];
    __syncthreads();
    bool up = ((base & k) == 0);   // constant per chunk: k > SCHUNK
    for (int j = SCHUNK >> 1; j > 0; j >>= 1) {
        int i = ((t & ~(j - 1)) << 1) | (t & (j - 1));
        int l = i | j;
        unsigned long long a = sk[i], b = sk[l];
        if ((a > b) == up) { sk[i] = b; sk[l] = a; }
        __syncthreads();
    }
    g_keys[base + t] = sk[t];
    g_keys[base + t + 1024] = sk[t + 1024];
}

// ------------------------------------------------------------------ pooling
__global__ void k_pool(const float* __restrict__ xin, int* __restrict__ perm,
                       float* __restrict__ xout, int kk) {
    int wid  = (blockIdx.x * blockDim.x + threadIdx.x) >> 5;
    int lane = threadIdx.x & 31;
    if (wid >= kk) return;
    int p = (int)(g_keys[wid] & 0xFFFFFFFFULL);
    float val = g_score[p];
    if (lane == 0) perm[wid] = p;
    float4 v = *(const float4*)(xin + (size_t)p * C + lane * 4);
    v.x *= val; v.y *= val; v.z *= val; v.w *= val;
    *(float4*)(xout + (size_t)wid * C + lane * 4) = v;
}

__global__ void k_seti(int* ptr, int cnt, int val) {
    int i = blockIdx.x * blockDim.x + threadIdx.x;
    if (i < cnt) ptr[i] = val;
}

__global__ void k_nmap_scatter(const int* __restrict__ perm, int kk) {
    int i = blockIdx.x * blockDim.x + threadIdx.x;
    if (i < kk) g_nmap[perm[i]] = i;
}

__global__ void k_remap(const int* __restrict__ sin, const int* __restrict__ rin,
                        int cntConst, const int* cntDev, int kk,
                        int* __restrict__ sout, int* __restrict__ rout, int* cntOut) {
    int e = blockIdx.x * blockDim.x + threadIdx.x;
    int cnt = cntDev ? __ldg(cntDev) : cntConst;
    if (e >= cnt) return;
    int ns = g_nmap[sin[e]];
    int nr = g_nmap[rin[e]];
    if (ns < kk && nr < kk) {
        int pos = atomicAdd(cntOut, 1);
        sout[pos] = ns;
        rout[pos] = nr;
    }
}

// ------------------------------------------------------------------ CSR build
__global__ void k_hist(const int* __restrict__ s, const int* __restrict__ r,
                       int cntConst, const int* cntDev) {
    int e = blockIdx.x * blockDim.x + threadIdx.x;
    int cnt = cntDev ? __ldg(cntDev) : cntConst;
    if (e >= cnt) return;
    atomicAdd(&g_deg[r[e]], 1);
    atomicAdd(&g_deg[s[e]], 1);
}

__global__ void k_scan(int nn, int* __restrict__ rowptr) {
    __shared__ int sh[1024];
    int t = threadIdx.x;
    if (t == 0) rowptr[0] = 0;
    int offset = 0;
    for (int base = 0; base < nn; base += 1024) {
        int v = (base + t < nn) ? g_deg[base + t] : 0;
        sh[t] = v;
        __syncthreads();
        for (int d = 1; d < 1024; d <<= 1) {
            int add = (t >= d) ? sh[t - d] : 0;
            __syncthreads();
            sh[t] += add;
            __syncthreads();
        }
        if (base + t < nn) rowptr[base + t + 1] = sh[t] + offset;
        offset += sh[1023];
        __syncthreads();
    }
    for (int i = t; i <= nn; i += 1024) g_cursor[i] = rowptr[i];
}

__global__ void k_fill(const int* __restrict__ s, const int* __restrict__ r,
                       int cntConst, const int* cntDev, int* __restrict__ col) {
    int e = blockIdx.x * blockDim.x + threadIdx.x;
    int cnt = cntDev ? __ldg(cntDev) : cntConst;
    if (e >= cnt) return;
    int se = s[e], re = r[e];
    int p1 = atomicAdd(&g_cursor[re], 1); col[p1] = se;
    int p2 = atomicAdd(&g_cursor[se], 1); col[p2] = re;
}

// ------------------------------------------------------------------ aggregation (gather CSR)
template <int CH>
__global__ void k_agg(const int* __restrict__ rowptr, const int* __restrict__ colv,
                      const float* __restrict__ x, float* __restrict__ out, int nn) {
    int w    = (blockIdx.x * blockDim.x + threadIdx.x) >> 5;
    int lane = threadIdx.x & 31;
    if (w >= nn) return;
    int beg = rowptr[w], end = rowptr[w + 1];
    const int F = CH / 32;
    float acc[F];
    #pragma unroll
    for (int i = 0; i < F; i++) acc[i] = 0.f;
    for (int e = beg; e < end; e++) {
        int u = __ldg(colv + e);
        const float4* p = (const float4*)(x + (size_t)u * CH + lane * F);
        #pragma unroll
        for (int q = 0; q < F / 4; q++) {
            float4 v = __ldg(p + q);
            acc[4 * q + 0] += v.x;
            acc[4 * q + 1] += v.y;
            acc[4 * q + 2] += v.z;
            acc[4 * q + 3] += v.w;
        }
    }
    float4* o = (float4*)(out + (size_t)w * CH + lane * F);
    #pragma unroll
    for (int q = 0; q < F / 4; q++)
        o[q] = make_float4(acc[4 * q], acc[4 * q + 1], acc[4 * q + 2], acc[4 * q + 3]);
}

// ------------------------------------------------------------------ GEMM (M x K @ K x 128 + bias [+gelu])
template <int ACT>
__global__ __launch_bounds__(256) void k_gemm(const float* __restrict__ A,
                                              const float* __restrict__ W,
                                              const float* __restrict__ bias,
                                              float* __restrict__ out, int M, int K) {
    __shared__ float As[8][128];
    __shared__ float Bs[8][128];
    int tid = threadIdx.x;
    int row0 = blockIdx.x * 128;
    int tx = tid & 15, ty = tid >> 4;
    float acc[8][8];
    #pragma unroll
    for (int i = 0; i < 8; i++)
        #pragma unroll
        for (int j = 0; j < 8; j++) acc[i][j] = 0.f;

    int ar = tid >> 1;
    int ac = (tid & 1) * 4;
    int br = tid >> 5;
    int bc = (tid & 31) * 4;

    for (int k0 = 0; k0 < K; k0 += 8) {
        int r = row0 + ar;
        float4 av = (r < M) ? *(const float4*)(A + (size_t)r * K + k0 + ac)
                            : make_float4(0.f, 0.f, 0.f, 0.f);
        As[ac + 0][ar] = av.x;
        As[ac + 1][ar] = av.y;
        As[ac + 2][ar] = av.z;
        As[ac + 3][ar] = av.w;
        *(float4*)&Bs[br][bc] = *(const float4*)(W + (size_t)(k0 + br) * 128 + bc);
        __syncthreads();
        #pragma unroll
        for (int kk = 0; kk < 8; kk++) {
            float a[8], b[8];
            *(float4*)&a[0] = *(float4*)&As[kk][ty * 8];
            *(float4*)&a[4] = *(float4*)&As[kk][ty * 8 + 4];
            *(float4*)&b[0] = *(float4*)&Bs[kk][tx * 8];
            *(float4*)&b[4] = *(float4*)&Bs[kk][tx * 8 + 4];
            #pragma unroll
            for (int i = 0; i < 8; i++)
                #pragma unroll
                for (int j = 0; j < 8; j++) acc[i][j] += a[i] * b[j];
        }
        __syncthreads();
    }
    float bv[8];
    *(float4*)&bv[0] = *(const float4*)(bias + tx * 8);
    *(float4*)&bv[4] = *(const float4*)(bias + tx * 8 + 4);
    #pragma unroll
    for (int i = 0; i < 8; i++) {
        int r = row0 + ty * 8 + i;
        if (r >= M) continue;
        float o[8];
        #pragma unroll
        for (int j = 0; j < 8; j++) {
            float v = acc[i][j] + bv[j];
            if (ACT) v = gelu_exact(v);
            o[j] = v;
        }
        *(float4*)(out + (size_t)r * 128 + tx * 8)     = *(float4*)&o[0];
        *(float4*)(out + (size_t)r * 128 + tx * 8 + 4) = *(float4*)&o[4];
    }
}

// ------------------------------------------------------------------ LayerNorm
__global__ void k_ln(const float* __restrict__ h, const float* __restrict__ g,
                     const float* __restrict__ b, float* __restrict__ out, int M) {
    int w    = (blockIdx.x * blockDim.x + threadIdx.x) >> 5;
    int lane = threadIdx.x & 31;
    if (w >= M) return;
    float4 v = *(const float4*)(h + (size_t)w * C + lane * 4);
    float s = warp_sum(v.x + v.y + v.z + v.w);
    float mu = s * (1.0f / 128.0f);
    float dx = v.x - mu, dy = v.y - mu, dz = v.z - mu, dw = v.w - mu;
    float q = warp_sum(dx * dx + dy * dy + dz * dz + dw * dw);
    float rs = rsqrtf(q * (1.0f / 128.0f) + 1e-5f);
    float4 gv = *(const float4*)(g + lane * 4);
    float4 bv = *(const float4*)(b + lane * 4);
    float4 o;
    o.x = gv.x * dx * rs + bv.x;
    o.y = gv.y * dy * rs + bv.y;
    o.z = gv.z * dz * rs + bv.z;
    o.w = gv.w * dw * rs + bv.w;
    *(float4*)(out + (size_t)w * C + lane * 4) = o;
}

// ------------------------------------------------------------------ up-path feature build
__global__ void k_featcopy(const float* __restrict__ res, int nn) {
    int w    = (blockIdx.x * blockDim.x + threadIdx.x) >> 5;
    int lane = threadIdx.x & 31;
    if (w >= nn) return;
    float4 v = *(const float4*)(res + (size_t)w * C + lane * 4);
    *(float4*)(g_feat + (size_t)w * C2 + lane * 4) = v;
    *(float4*)(g_feat + (size_t)w * C2 + C + lane * 4) = make_float4(0.f, 0.f, 0.f, 0.f);
}

__global__ void k_featscatter(const int* __restrict__ perm, const float* __restrict__ xc, int kk) {
    int w    = (blockIdx.x * blockDim.x + threadIdx.x) >> 5;
    int lane = threadIdx.x & 31;
    if (w >= kk) return;
    int p = perm[w];
    float4 v = *(const float4*)(xc + (size_t)w * C + lane * 4);
    *(float4*)(g_feat + (size_t)p * C2 + C + lane * 4) = v;
}

// ------------------------------------------------------------------ host
static inline int divup(int a, int b) { return (a + b - 1) / b; }

extern "C" void kernel_launch(void* const* d_in, const int* in_sizes, int n_in,
                              void* d_out, int out_size) {
    const float* x0  = (const float*)d_in[0];
    const int*   s0  = (const int*)d_in[1];
    const int*   r0  = (const int*)d_in[2];
    const float* pw  = (const float*)d_in[3];
    const float* dW1 = (const float*)d_in[4];
    const float* db1 = (const float*)d_in[5];
    const float* dW2 = (const float*)d_in[6];
    const float* db2 = (const float*)d_in[7];
    const float* dW3 = (const float*)d_in[8];
    const float* db3 = (const float*)d_in[9];
    const float* dg  = (const float*)d_in[10];
    const float* dbt = (const float*)d_in[11];
    const float* uW1 = (const float*)d_in[12];
    const float* ub1 = (const float*)d_in[13];
    const float* uW2 = (const float*)d_in[14];
    const float* ub2 = (const float*)d_in[15];
    const float* uW3 = (const float*)d_in[16];
    const float* ub3 = (const float*)d_in[17];
    const float* ug  = (const float*)d_in[18];
    const float* ubt = (const float*)d_in[19];

    int N = in_sizes[0] / C;
    int E = in_sizes[1];
    int n[4];
    n[0] = N;
    for (int i = 0; i < 3; i++) n[i + 1] = (n[i] + 1) / 2;

    void* p;
    float *xs1, *xs2, *xpool, *agg, *feat, *h1, *h2, *xd3, *xu0, *xu1;
    int *permbuf, *nmap, *es, *er, *ecnt, *col, *rowptr, *deg;
    cudaGetSymbolAddress(&p, g_xs1);     xs1 = (float*)p;
    cudaGetSymbolAddress(&p, g_xs2);     xs2 = (float*)p;
    cudaGetSymbolAddress(&p, g_xpool);   xpool = (float*)p;
    cudaGetSymbolAddress(&p, g_agg);     agg = (float*)p;
    cudaGetSymbolAddress(&p, g_feat);    feat = (float*)p;
    cudaGetSymbolAddress(&p, g_h1);      h1 = (float*)p;
    cudaGetSymbolAddress(&p, g_h2);      h2 = (float*)p;
    cudaGetSymbolAddress(&p, g_xd3);     xd3 = (float*)p;
    cudaGetSymbolAddress(&p, g_xu0);     xu0 = (float*)p;
    cudaGetSymbolAddress(&p, g_xu1);     xu1 = (float*)p;
    cudaGetSymbolAddress(&p, g_permbuf); permbuf = (int*)p;
    cudaGetSymbolAddress(&p, g_nmap);    nmap = (int*)p;
    cudaGetSymbolAddress(&p, g_es);      es = (int*)p;
    cudaGetSymbolAddress(&p, g_er);      er = (int*)p;
    cudaGetSymbolAddress(&p, g_ecnt);    ecnt = (int*)p;
    cudaGetSymbolAddress(&p, g_col);     col = (int*)p;
    cudaGetSymbolAddress(&p, g_rowptr);  rowptr = (int*)p;
    cudaGetSymbolAddress(&p, g_deg);     deg = (int*)p;

    int egrid = divup(E, TPB);

    // CSR build for edge set `set` over nodes [0, nn)
    auto build_csr = [&](int set, const int* s, const int* r, int cntConst,
                         const int* cntDev, int nn) {
        int* rp = rowptr + set * (MAXN + 2);
        int* cl = col + (size_t)set * 2 * MAXE;
        k_seti<<<divup(nn + 1, TPB), TPB>>>(deg, nn + 1, 0);
        k_hist<<<egrid, TPB>>>(s, r, cntConst, cntDev);
        k_scan<<<1, 1024>>>(nn, rp);
        k_fill<<<egrid, TPB>>>(s, r, cntConst, cntDev, cl);
    };

    // perm offsets
    int poff[3] = {0, n[1], n[1] + n[2]};

    // CSR set 0: original edges
    build_csr(0, s0, r0, E, nullptr, N);

    // -------------------------------------------------- down path
    const float* xin = x0;
    float* xsbuf[3] = {xs1, xs2, xd3};
    for (int i = 0; i < 3; i++) {
        int nn = n[i], kk = n[i + 1];
        int P = 1;
        while (P < nn) P <<= 1;

        k_score<<<divup(nn, 8), TPB>>>(xin, pw + i * C, nn);
        k_keyinit<<<divup(P, TPB), TPB>>>(nn, P);
        // bitonic sort (ascending composite key)
        k_sort_local_full<<<P / SCHUNK, 1024>>>();
        for (int k2 = SCHUNK * 2; k2 <= P; k2 <<= 1) {
            for (int j = k2 >> 1; j >= SCHUNK; j >>= 1)
                k_sort_global<<<divup(P / 2, TPB), TPB>>>(j, k2, P);
            k_sort_local_merge<<<P / SCHUNK, 1024>>>(k2);
        }

        int* perm = permbuf + poff[i];
        k_pool<<<divup(kk, 8), TPB>>>(xin, perm, xpool, kk);

        // nmap + edge remap/compact
        k_seti<<<divup(nn + 1, TPB), TPB>>>(nmap, nn + 1, kk);
        k_nmap_scatter<<<divup(kk, TPB), TPB>>>(perm, kk);
        k_seti<<<1, 32>>>(ecnt + i, 1, 0);
        const int* sin = (i == 0) ? s0 : (es + (i - 1) * MAXE);
        const int* rin = (i == 0) ? r0 : (er + (i - 1) * MAXE);
        const int* cd  = (i == 0) ? nullptr : (ecnt + (i - 1));
        k_remap<<<egrid, TPB>>>(sin, rin, (i == 0) ? E : 0, cd, kk,
                                es + i * MAXE, er + i * MAXE, ecnt + i);

        // CSR set i+1 over kk nodes
        build_csr(i + 1, es + i * MAXE, er + i * MAXE, 0, ecnt + i, kk);

        // aggregation + MLP + LN
        k_agg<128><<<divup(kk, 8), TPB>>>(rowptr + (i + 1) * (MAXN + 2),
                                          col + (size_t)(i + 1) * 2 * MAXE, xpool, agg, kk);
        k_gemm<1><<<divup(kk, 128), 256>>>(agg, dW1 + i * C * C, db1 + i * C, h1, kk, C);
        k_gemm<1><<<divup(kk, 128), 256>>>(h1, dW2 + i * C * C, db2 + i * C, h2, kk, C);
        k_gemm<0><<<divup(kk, 128), 256>>>(h2, dW3 + i * C * C, db3 + i * C, h1, kk, C);
        k_ln<<<divup(kk, 8), TPB>>>(h1, dg + i * C, dbt + i * C, xsbuf[i], kk);

        xin = xsbuf[i];
    }

    // -------------------------------------------------- up path
    const float* xcur = xd3;
    for (int i = 0; i < 3; i++) {
        int j = 2 - i;
        int nn = n[j];       // rows of residual / output
        int kk = n[j + 1];   // rows of current x
        const float* res = (j == 0) ? x0 : ((j == 1) ? xs1 : xs2);
        const int* perm = permbuf + poff[j];

        k_featcopy<<<divup(nn, 8), TPB>>>(res, nn);
        k_featscatter<<<divup(kk, 8), TPB>>>(perm, xcur, kk);

        k_agg<256><<<divup(nn, 8), TPB>>>(rowptr + j * (MAXN + 2),
                                          col + (size_t)j * 2 * MAXE, feat, agg, nn);
        k_gemm<1><<<divup(nn, 128), 256>>>(agg, uW1 + i * C2 * C, ub1 + i * C, h1, nn, C2);
        k_gemm<1><<<divup(nn, 128), 256>>>(h1, uW2 + i * C * C, ub2 + i * C, h2, nn, C);
        k_gemm<0><<<divup(nn, 128), 256>>>(h2, uW3 + i * C * C, ub3 + i * C, h1, nn, C);

        float* outp = (i == 2) ? (float*)d_out : ((i == 0) ? xu0 : xu1);
        k_ln<<<divup(nn, 8), TPB>>>(h1, ug + i * C, ubt + i * C, outp, nn);
        xcur = outp;
    }
}

// round 13
// speedup vs baseline: 1.0793x; 1.0793x over previous
#include <cuda_runtime.h>
#include <math.h>

#define C    128
#define C2   256
#define MAXN 50000
#define MAXE 600000
#define PADMAX 65536
#define SCHUNK 2048
#define TPB  256

// ------------------------------------------------------------------ scratch
__device__ float g_score[MAXN];
__device__ unsigned long long g_keys[PADMAX];
__device__ int   g_permbuf[MAXN];
__device__ float g_xs1[25088 * C];
__device__ float g_xs2[12544 * C];
__device__ float g_xpool[25088 * C];
__device__ float g_agg[MAXN * C2];
__device__ float g_feat[MAXN * C2];
__device__ float g_h1[MAXN * C];
__device__ float g_h2[MAXN * C];
__device__ float g_xd3[6272 * C];
__device__ float g_xu0[12544 * C];
__device__ float g_xu1[25088 * C];
__device__ int g_nmap[MAXN + 1];
__device__ int g_es[3 * MAXE];
__device__ int g_er[3 * MAXE];
__device__ int g_ecnt[4];
__device__ int g_col[4 * 2 * MAXE];
__device__ int g_rowptr[4 * (MAXN + 2)];
__device__ int g_deg[MAXN + 1];
__device__ int g_cursor[MAXN + 1];

// ------------------------------------------------------------------ helpers
__device__ __forceinline__ float warp_sum(float v) {
    #pragma unroll
    for (int o = 16; o; o >>= 1) v += __shfl_xor_sync(0xffffffffu, v, o);
    return v;
}

__device__ __forceinline__ float gelu_exact(float v) {
    return 0.5f * v * (1.0f + erff(v * 0.70710678118654752f));
}

__device__ __forceinline__ void ffma2(unsigned long long& d,
                                      unsigned long long a,
                                      unsigned long long b) {
    asm("fma.rn.f32x2 %0, %1, %2, %0;" : "+l"(d) : "l"(a), "l"(b));
}

// ------------------------------------------------------------------ scoring
__global__ void k_score(const float* __restrict__ x, const float* __restrict__ w, int nn) {
    int wid  = (blockIdx.x * blockDim.x + threadIdx.x) >> 5;
    int lane = threadIdx.x & 31;
    if (wid >= nn) return;
    float4 wv = *(const float4*)(w + lane * 4);
    float4 xv = *(const float4*)(x + (size_t)wid * C + lane * 4);
    float dot = xv.x * wv.x + xv.y * wv.y + xv.z * wv.z + xv.w * wv.w;
    float nrm = wv.x * wv.x + wv.y * wv.y + wv.z * wv.z + wv.w * wv.w;
    dot = warp_sum(dot);
    nrm = warp_sum(nrm);
    if (lane == 0) g_score[wid] = tanhf(dot / sqrtf(nrm));
}

// ------------------------------------------------------------------ top-k sort
__global__ void k_keyinit(int nn, int P) {
    int i = blockIdx.x * blockDim.x + threadIdx.x;
    if (i >= P) return;
    unsigned long long kk;
    if (i < nn) {
        unsigned u = __float_as_uint(g_score[i]);
        u = (u & 0x80000000u) ? ~u : (u | 0x80000000u);
        kk = (((unsigned long long)(~u)) << 32) | (unsigned)i;
    } else {
        kk = 0xFFFFFFFFFFFFFFFFULL;
    }
    g_keys[i] = kk;
}

__global__ void k_sort_local_full() {
    __shared__ unsigned long long sk[SCHUNK];
    int base = blockIdx.x * SCHUNK;
    int t = threadIdx.x;
    sk[t] = g_keys[base + t];
    sk[t + 1024] = g_keys[base + t + 1024];
    __syncthreads();
    for (int k = 2; k <= SCHUNK; k <<= 1) {
        for (int j = k >> 1; j > 0; j >>= 1) {
            int i = ((t & ~(j - 1)) << 1) | (t & (j - 1));
            int l = i | j;
            bool up = (((base + i) & k) == 0);
            unsigned long long a = sk[i], b = sk[l];
            if ((a > b) == up) { sk[i] = b; sk[l] = a; }
            __syncthreads();
        }
    }
    g_keys[base + t] = sk[t];
    g_keys[base + t + 1024] = sk[t + 1024];
}

__global__ void k_sort_global(int j, int k, int P) {
    int t = blockIdx.x * blockDim.x + threadIdx.x;
    if (t >= (P >> 1)) return;
    int i = ((t & ~(j - 1)) << 1) | (t & (j - 1));
    int l = i | j;
    bool up = ((i & k) == 0);
    unsigned long long a = g_keys[i], b = g_keys[l];
    if ((a > b) == up) { g_keys[i] = b; g_keys[l] = a; }
}

__global__ void k_sort_local_merge(int k) {
    __shared__ unsigned long long sk[SCHUNK];
    int base = blockIdx.x * SCHUNK;
    int t = threadIdx.x;
    sk[t] = g_keys[base + t];
    sk[t + 1024] = g_keys[base + t + 1024];
    __syncthreads();
    bool up = ((base & k) == 0);
    for (int j = SCHUNK >> 1; j > 0; j >>= 1) {
        int i = ((t & ~(j - 1)) << 1) | (t & (j - 1));
        int l = i | j;
        unsigned long long a = sk[i], b = sk[l];
        if ((a > b) == up) { sk[i] = b; sk[l] = a; }
        __syncthreads();
    }
    g_keys[base + t] = sk[t];
    g_keys[base + t + 1024] = sk[t + 1024];
}

// ------------------------------------------------------------------ pooling
__global__ void k_pool(const float* __restrict__ xin, int* __restrict__ perm,
                       float* __restrict__ xout, int kk) {
    int wid  = (blockIdx.x * blockDim.x + threadIdx.x) >> 5;
    int lane = threadIdx.x & 31;
    if (wid >= kk) return;
    int p = (int)(g_keys[wid] & 0xFFFFFFFFULL);
    float val = g_score[p];
    if (lane == 0) perm[wid] = p;
    float4 v = *(const float4*)(xin + (size_t)p * C + lane * 4);
    v.x *= val; v.y *= val; v.z *= val; v.w *= val;
    *(float4*)(xout + (size_t)wid * C + lane * 4) = v;
}

__global__ void k_seti(int* ptr, int cnt, int val) {
    int i = blockIdx.x * blockDim.x + threadIdx.x;
    if (i < cnt) ptr[i] = val;
}

__global__ void k_nmap_scatter(const int* __restrict__ perm, int kk) {
    int i = blockIdx.x * blockDim.x + threadIdx.x;
    if (i < kk) g_nmap[perm[i]] = i;
}

// warp-aggregated stream compaction
__global__ void k_remap(const int* __restrict__ sin, const int* __restrict__ rin,
                        int cntConst, const int* cntDev, int kk,
                        int* __restrict__ sout, int* __restrict__ rout, int* cntOut) {
    int e = blockIdx.x * blockDim.x + threadIdx.x;
    int cnt = cntDev ? __ldg(cntDev) : cntConst;
    bool valid = false;
    int ns = 0, nr = 0;
    if (e < cnt) {
        ns = g_nmap[sin[e]];
        nr = g_nmap[rin[e]];
        valid = (ns < kk) && (nr < kk);
    }
    unsigned mask = __ballot_sync(0xffffffffu, valid);
    if (!valid) return;
    int lane = threadIdx.x & 31;
    int leader = __ffs(mask) - 1;
    int rank = __popc(mask & ((1u << lane) - 1));
    int base = 0;
    if (lane == leader) base = atomicAdd(cntOut, __popc(mask));
    base = __shfl_sync(mask, base, leader);
    sout[base + rank] = ns;
    rout[base + rank] = nr;
}

// ------------------------------------------------------------------ CSR build
__global__ void k_hist(const int* __restrict__ s, const int* __restrict__ r,
                       int cntConst, const int* cntDev) {
    int e = blockIdx.x * blockDim.x + threadIdx.x;
    int cnt = cntDev ? __ldg(cntDev) : cntConst;
    if (e >= cnt) return;
    atomicAdd(&g_deg[r[e]], 1);
    atomicAdd(&g_deg[s[e]], 1);
}

__global__ void k_scan(int nn, int* __restrict__ rowptr) {
    __shared__ int warpsum[32];
    __shared__ int carry;
    int t = threadIdx.x, lane = t & 31, wid = t >> 5;
    if (t == 0) { rowptr[0] = 0; carry = 0; }
    __syncthreads();
    for (int base = 0; base < nn; base += 1024) {
        int v = (base + t < nn) ? g_deg[base + t] : 0;
        int x = v;
        #pragma unroll
        for (int o = 1; o < 32; o <<= 1) {
            int y = __shfl_up_sync(0xffffffffu, x, o);
            if (lane >= o) x += y;
        }
        if (lane == 31) warpsum[wid] = x;
        __syncthreads();
        if (wid == 0) {
            int s = warpsum[lane];
            #pragma unroll
            for (int o = 1; o < 32; o <<= 1) {
                int y = __shfl_up_sync(0xffffffffu, s, o);
                if (lane >= o) s += y;
            }
            warpsum[lane] = s;
        }
        __syncthreads();
        int off = carry + (wid ? warpsum[wid - 1] : 0);
        if (base + t < nn) rowptr[base + t + 1] = off + x;
        int total = warpsum[31];
        __syncthreads();
        if (t == 0) carry += total;
        __syncthreads();
    }
    for (int i = t; i <= nn; i += 1024) g_cursor[i] = rowptr[i];
}

__global__ void k_fill(const int* __restrict__ s, const int* __restrict__ r,
                       int cntConst, const int* cntDev, int* __restrict__ col) {
    int e = blockIdx.x * blockDim.x + threadIdx.x;
    int cnt = cntDev ? __ldg(cntDev) : cntConst;
    if (e >= cnt) return;
    int se = s[e], re = r[e];
    int p1 = atomicAdd(&g_cursor[re], 1); col[p1] = se;
    int p2 = atomicAdd(&g_cursor[se], 1); col[p2] = re;
}

// ------------------------------------------------------------------ aggregation (gather CSR)
template <int CH>
__global__ void k_agg(const int* __restrict__ rowptr, const int* __restrict__ colv,
                      const float* __restrict__ x, float* __restrict__ out, int nn) {
    int w    = (blockIdx.x * blockDim.x + threadIdx.x) >> 5;
    int lane = threadIdx.x & 31;
    if (w >= nn) return;
    int beg = rowptr[w], end = rowptr[w + 1];
    const int F = CH / 32;
    float acc[F];
    #pragma unroll
    for (int i = 0; i < F; i++) acc[i] = 0.f;
    for (int e = beg; e < end; e++) {
        int u = __ldg(colv + e);
        const float4* p = (const float4*)(x + (size_t)u * CH + lane * F);
        #pragma unroll
        for (int q = 0; q < F / 4; q++) {
            float4 v = __ldg(p + q);
            acc[4 * q + 0] += v.x;
            acc[4 * q + 1] += v.y;
            acc[4 * q + 2] += v.z;
            acc[4 * q + 3] += v.w;
        }
    }
    float4* o = (float4*)(out + (size_t)w * CH + lane * F);
    #pragma unroll
    for (int q = 0; q < F / 4; q++)
        o[q] = make_float4(acc[4 * q], acc[4 * q + 1], acc[4 * q + 2], acc[4 * q + 3]);
}

// ------------------------------------------------------------------ GEMM (M x K @ K x 128 + bias [+gelu])
// f32x2 packed FMA, 128x128 tile, KT=16, double-buffered smem.
// Rows packed pairwise in accumulator halves; Bs duplicated in quarter layout
// so all LDS are conflict-free (As is broadcast).
template <int ACT>
__global__ __launch_bounds__(256, 2) void k_gemm(const float* __restrict__ A,
                                                 const float* __restrict__ W,
                                                 const float* __restrict__ bias,
                                                 float* __restrict__ out, int M, int K) {
    __shared__ float As[2][16][128];        // [buf][kk][m]
    __shared__ float Bs[2][16][4][64];      // [buf][kk][q][tx*4+e]  (duplicated pairs)
    const int tid = threadIdx.x;
    const int row0 = blockIdx.x * 128;
    const int tx = tid & 15, ty = tid >> 4;

    // A staging: thread loads 8 floats of one row
    const int ar = tid >> 1;
    const int ac = (tid & 1) * 8;
    // W staging: thread loads rows wr, wr+8, 4 cols each
    const int wr = tid >> 5;
    const int wc = (tid & 31) * 4;
    const int wtx = wc >> 3;
    const int wq = (wc & 7) >> 1;    // 0 or 2

    const int nt = K >> 4;
    const int arow = row0 + ar;
    const bool aval = (arow < M);
    const float* Aptr = A + (size_t)(aval ? arow : 0) * K + ac;

    unsigned long long acc[4][8];
    #pragma unroll
    for (int p = 0; p < 4; p++)
        #pragma unroll
        for (int j = 0; j < 8; j++) acc[p][j] = 0ULL;

    float4 a0, a1, w0, w1;
    if (aval) { a0 = *(const float4*)(Aptr); a1 = *(const float4*)(Aptr + 4); }
    else { a0 = make_float4(0.f, 0.f, 0.f, 0.f); a1 = a0; }
    w0 = *(const float4*)(W + (size_t)wr * 128 + wc);
    w1 = *(const float4*)(W + (size_t)(wr + 8) * 128 + wc);

    As[0][ac + 0][ar] = a0.x; As[0][ac + 1][ar] = a0.y;
    As[0][ac + 2][ar] = a0.z; As[0][ac + 3][ar] = a0.w;
    As[0][ac + 4][ar] = a1.x; As[0][ac + 5][ar] = a1.y;
    As[0][ac + 6][ar] = a1.z; As[0][ac + 7][ar] = a1.w;
    *(float4*)&Bs[0][wr][wq][wtx * 4]       = make_float4(w0.x, w0.x, w0.y, w0.y);
    *(float4*)&Bs[0][wr][wq + 1][wtx * 4]   = make_float4(w0.z, w0.z, w0.w, w0.w);
    *(float4*)&Bs[0][wr + 8][wq][wtx * 4]     = make_float4(w1.x, w1.x, w1.y, w1.y);
    *(float4*)&Bs[0][wr + 8][wq + 1][wtx * 4] = make_float4(w1.z, w1.z, w1.w, w1.w);
    __syncthreads();

    for (int t = 0; t < nt; t++) {
        const int cur = t & 1;
        if (t + 1 < nt) {
            int k0 = (t + 1) * 16;
            if (aval) { a0 = *(const float4*)(Aptr + k0); a1 = *(const float4*)(Aptr + k0 + 4); }
            w0 = *(const float4*)(W + (size_t)(k0 + wr) * 128 + wc);
            w1 = *(const float4*)(W + (size_t)(k0 + wr + 8) * 128 + wc);
        }
        #pragma unroll
        for (int kk = 0; kk < 16; kk++) {
            ulonglong2 av0 = *(const ulonglong2*)&As[cur][kk][ty * 8];
            ulonglong2 av1 = *(const ulonglong2*)&As[cur][kk][ty * 8 + 4];
            unsigned long long a2[4] = {av0.x, av0.y, av1.x, av1.y};
            unsigned long long b2[8];
            #pragma unroll
            for (int q = 0; q < 4; q++) {
                ulonglong2 bv = *(const ulonglong2*)&Bs[cur][kk][q][tx * 4];
                b2[2 * q] = bv.x;
                b2[2 * q + 1] = bv.y;
            }
            #pragma unroll
            for (int p = 0; p < 4; p++)
                #pragma unroll
                for (int j = 0; j < 8; j++) ffma2(acc[p][j], a2[p], b2[j]);
        }
        if (t + 1 < nt) {
            const int nb = 1 - cur;
            As[nb][ac + 0][ar] = a0.x; As[nb][ac + 1][ar] = a0.y;
            As[nb][ac + 2][ar] = a0.z; As[nb][ac + 3][ar] = a0.w;
            As[nb][ac + 4][ar] = a1.x; As[nb][ac + 5][ar] = a1.y;
            As[nb][ac + 6][ar] = a1.z; As[nb][ac + 7][ar] = a1.w;
            *(float4*)&Bs[nb][wr][wq][wtx * 4]       = make_float4(w0.x, w0.x, w0.y, w0.y);
            *(float4*)&Bs[nb][wr][wq + 1][wtx * 4]   = make_float4(w0.z, w0.z, w0.w, w0.w);
            *(float4*)&Bs[nb][wr + 8][wq][wtx * 4]     = make_float4(w1.x, w1.x, w1.y, w1.y);
            *(float4*)&Bs[nb][wr + 8][wq + 1][wtx * 4] = make_float4(w1.z, w1.z, w1.w, w1.w);
            __syncthreads();
        }
    }

    float bvv[8];
    *(float4*)&bvv[0] = *(const float4*)(bias + tx * 8);
    *(float4*)&bvv[4] = *(const float4*)(bias + tx * 8 + 4);
    #pragma unroll
    for (int p = 0; p < 4; p++) {
        int r0 = row0 + ty * 8 + 2 * p;
        float o0[8], o1[8];
        #pragma unroll
        for (int j = 0; j < 8; j++) {
            float2 u = *(float2*)&acc[p][j];
            float v0 = u.x + bvv[j];
            float v1 = u.y + bvv[j];
            if (ACT) { v0 = gelu_exact(v0); v1 = gelu_exact(v1); }
            o0[j] = v0; o1[j] = v1;
        }
        if (r0 < M) {
            *(float4*)(out + (size_t)r0 * 128 + tx * 8)     = *(float4*)&o0[0];
            *(float4*)(out + (size_t)r0 * 128 + tx * 8 + 4) = *(float4*)&o0[4];
        }
        if (r0 + 1 < M) {
            *(float4*)(out + (size_t)(r0 + 1) * 128 + tx * 8)     = *(float4*)&o1[0];
            *(float4*)(out + (size_t)(r0 + 1) * 128 + tx * 8 + 4) = *(float4*)&o1[4];
        }
    }
}

// ------------------------------------------------------------------ LayerNorm
__global__ void k_ln(const float* __restrict__ h, const float* __restrict__ g,
                     const float* __restrict__ b, float* __restrict__ out, int M) {
    int w    = (blockIdx.x * blockDim.x + threadIdx.x) >> 5;
    int lane = threadIdx.x & 31;
    if (w >= M) return;
    float4 v = *(const float4*)(h + (size_t)w * C + lane * 4);
    float s = warp_sum(v.x + v.y + v.z + v.w);
    float mu = s * (1.0f / 128.0f);
    float dx = v.x - mu, dy = v.y - mu, dz = v.z - mu, dw = v.w - mu;
    float q = warp_sum(dx * dx + dy * dy + dz * dz + dw * dw);
    float rs = rsqrtf(q * (1.0f / 128.0f) + 1e-5f);
    float4 gv = *(const float4*)(g + lane * 4);
    float4 bv = *(const float4*)(b + lane * 4);
    float4 o;
    o.x = gv.x * dx * rs + bv.x;
    o.y = gv.y * dy * rs + bv.y;
    o.z = gv.z * dz * rs + bv.z;
    o.w = gv.w * dw * rs + bv.w;
    *(float4*)(out + (size_t)w * C + lane * 4) = o;
}

// ------------------------------------------------------------------ up-path feature build
__global__ void k_featcopy(const float* __restrict__ res, int nn) {
    int w    = (blockIdx.x * blockDim.x + threadIdx.x) >> 5;
    int lane = threadIdx.x & 31;
    if (w >= nn) return;
    float4 v = *(const float4*)(res + (size_t)w * C + lane * 4);
    *(float4*)(g_feat + (size_t)w * C2 + lane * 4) = v;
    *(float4*)(g_feat + (size_t)w * C2 + C + lane * 4) = make_float4(0.f, 0.f, 0.f, 0.f);
}

__global__ void k_featscatter(const int* __restrict__ perm, const float* __restrict__ xc, int kk) {
    int w    = (blockIdx.x * blockDim.x + threadIdx.x) >> 5;
    int lane = threadIdx.x & 31;
    if (w >= kk) return;
    int p = perm[w];
    float4 v = *(const float4*)(xc + (size_t)w * C + lane * 4);
    *(float4*)(g_feat + (size_t)p * C2 + C + lane * 4) = v;
}

// ------------------------------------------------------------------ host
static inline int divup(int a, int b) { return (a + b - 1) / b; }

extern "C" void kernel_launch(void* const* d_in, const int* in_sizes, int n_in,
                              void* d_out, int out_size) {
    const float* x0  = (const float*)d_in[0];
    const int*   s0  = (const int*)d_in[1];
    const int*   r0  = (const int*)d_in[2];
    const float* pw  = (const float*)d_in[3];
    const float* dW1 = (const float*)d_in[4];
    const float* db1 = (const float*)d_in[5];
    const float* dW2 = (const float*)d_in[6];
    const float* db2 = (const float*)d_in[7];
    const float* dW3 = (const float*)d_in[8];
    const float* db3 = (const float*)d_in[9];
    const float* dg  = (const float*)d_in[10];
    const float* dbt = (const float*)d_in[11];
    const float* uW1 = (const float*)d_in[12];
    const float* ub1 = (const float*)d_in[13];
    const float* uW2 = (const float*)d_in[14];
    const float* ub2 = (const float*)d_in[15];
    const float* uW3 = (const float*)d_in[16];
    const float* ub3 = (const float*)d_in[17];
    const float* ug  = (const float*)d_in[18];
    const float* ubt = (const float*)d_in[19];

    int N = in_sizes[0] / C;
    int E = in_sizes[1];
    int n[4];
    n[0] = N;
    for (int i = 0; i < 3; i++) n[i + 1] = (n[i] + 1) / 2;

    void* p;
    float *xs1, *xs2, *xpool, *agg, *feat, *h1, *h2, *xd3, *xu0, *xu1;
    int *permbuf, *nmap, *es, *er, *ecnt, *col, *rowptr, *deg;
    cudaGetSymbolAddress(&p, g_xs1);     xs1 = (float*)p;
    cudaGetSymbolAddress(&p, g_xs2);     xs2 = (float*)p;
    cudaGetSymbolAddress(&p, g_xpool);   xpool = (float*)p;
    cudaGetSymbolAddress(&p, g_agg);     agg = (float*)p;
    cudaGetSymbolAddress(&p, g_feat);    feat = (float*)p;
    cudaGetSymbolAddress(&p, g_h1);      h1 = (float*)p;
    cudaGetSymbolAddress(&p, g_h2);      h2 = (float*)p;
    cudaGetSymbolAddress(&p, g_xd3);     xd3 = (float*)p;
    cudaGetSymbolAddress(&p, g_xu0);     xu0 = (float*)p;
    cudaGetSymbolAddress(&p, g_xu1);     xu1 = (float*)p;
    cudaGetSymbolAddress(&p, g_permbuf); permbuf = (int*)p;
    cudaGetSymbolAddress(&p, g_nmap);    nmap = (int*)p;
    cudaGetSymbolAddress(&p, g_es);      es = (int*)p;
    cudaGetSymbolAddress(&p, g_er);      er = (int*)p;
    cudaGetSymbolAddress(&p, g_ecnt);    ecnt = (int*)p;
    cudaGetSymbolAddress(&p, g_col);     col = (int*)p;
    cudaGetSymbolAddress(&p, g_rowptr);  rowptr = (int*)p;
    cudaGetSymbolAddress(&p, g_deg);     deg = (int*)p;

    int egrid = divup(E, TPB);

    auto build_csr = [&](int set, const int* s, const int* r, int cntConst,
                         const int* cntDev, int nn) {
        int* rp = rowptr + set * (MAXN + 2);
        int* cl = col + (size_t)set * 2 * MAXE;
        k_seti<<<divup(nn + 1, TPB), TPB>>>(deg, nn + 1, 0);
        k_hist<<<egrid, TPB>>>(s, r, cntConst, cntDev);
        k_scan<<<1, 1024>>>(nn, rp);
        k_fill<<<egrid, TPB>>>(s, r, cntConst, cntDev, cl);
    };

    int poff[3] = {0, n[1], n[1] + n[2]};

    build_csr(0, s0, r0, E, nullptr, N);

    // -------------------------------------------------- down path
    const float* xin = x0;
    float* xsbuf[3] = {xs1, xs2, xd3};
    for (int i = 0; i < 3; i++) {
        int nn = n[i], kk = n[i + 1];
        int P = 1;
        while (P < nn) P <<= 1;

        k_score<<<divup(nn, 8), TPB>>>(xin, pw + i * C, nn);
        k_keyinit<<<divup(P, TPB), TPB>>>(nn, P);
        k_sort_local_full<<<P / SCHUNK, 1024>>>();
        for (int k2 = SCHUNK * 2; k2 <= P; k2 <<= 1) {
            for (int j = k2 >> 1; j >= SCHUNK; j >>= 1)
                k_sort_global<<<divup(P / 2, TPB), TPB>>>(j, k2, P);
            k_sort_local_merge<<<P / SCHUNK, 1024>>>(k2);
        }

        int* perm = permbuf + poff[i];
        k_pool<<<divup(kk, 8), TPB>>>(xin, perm, xpool, kk);

        k_seti<<<divup(nn + 1, TPB), TPB>>>(nmap, nn + 1, kk);
        k_nmap_scatter<<<divup(kk, TPB), TPB>>>(perm, kk);
        k_seti<<<1, 32>>>(ecnt + i, 1, 0);
        const int* sin = (i == 0) ? s0 : (es + (i - 1) * MAXE);
        const int* rin = (i == 0) ? r0 : (er + (i - 1) * MAXE);
        const int* cd  = (i == 0) ? nullptr : (ecnt + (i - 1));
        k_remap<<<egrid, TPB>>>(sin, rin, (i == 0) ? E : 0, cd, kk,
                                es + i * MAXE, er + i * MAXE, ecnt + i);

        build_csr(i + 1, es + i * MAXE, er + i * MAXE, 0, ecnt + i, kk);

        k_agg<128><<<divup(kk, 8), TPB>>>(rowptr + (i + 1) * (MAXN + 2),
                                          col + (size_t)(i + 1) * 2 * MAXE, xpool, agg, kk);
        k_gemm<1><<<divup(kk, 128), 256>>>(agg, dW1 + i * C * C, db1 + i * C, h1, kk, C);
        k_gemm<1><<<divup(kk, 128), 256>>>(h1, dW2 + i * C * C, db2 + i * C, h2, kk, C);
        k_gemm<0><<<divup(kk, 128), 256>>>(h2, dW3 + i * C * C, db3 + i * C, h1, kk, C);
        k_ln<<<divup(kk, 8), TPB>>>(h1, dg + i * C, dbt + i * C, xsbuf[i], kk);

        xin = xsbuf[i];
    }

    // -------------------------------------------------- up path
    const float* xcur = xd3;
    for (int i = 0; i < 3; i++) {
        int j = 2 - i;
        int nn = n[j];
        int kk = n[j + 1];
        const float* res = (j == 0) ? x0 : ((j == 1) ? xs1 : xs2);
        const int* perm = permbuf + poff[j];

        k_featcopy<<<divup(nn, 8), TPB>>>(res, nn);
        k_featscatter<<<divup(kk, 8), TPB>>>(perm, xcur, kk);

        k_agg<256><<<divup(nn, 8), TPB>>>(rowptr + j * (MAXN + 2),
                                          col + (size_t)j * 2 * MAXE, feat, agg, nn);
        k_gemm<1><<<divup(nn, 128), 256>>>(agg, uW1 + i * C2 * C, ub1 + i * C, h1, nn, C2);
        k_gemm<1><<<divup(nn, 128), 256>>>(h1, uW2 + i * C * C, ub2 + i * C, h2, nn, C);
        k_gemm<0><<<divup(nn, 128), 256>>>(h2, uW3 + i * C * C, ub3 + i * C, h1, nn, C);

        float* outp = (i == 2) ? (float*)d_out : ((i == 0) ? xu0 : xu1);
        k_ln<<<divup(nn, 8), TPB>>>(h1, ug + i * C, ubt + i * C, outp, nn);
        xcur = outp;
    }
}

// round 14
// speedup vs baseline: 1.0818x; 1.0023x over previous
#include <cuda_runtime.h>
#include <math.h>

#define C    128
#define C2   256
#define MAXN 50000
#define MAXE 600000
#define PADMAX 65536
#define SCHUNK 2048
#define TPB  256

// ------------------------------------------------------------------ scratch
__device__ float g_score[MAXN];
__device__ unsigned long long g_keys[PADMAX];
__device__ int   g_permbuf[MAXN];
__device__ float g_xs1[25088 * C];
__device__ float g_xs2[12544 * C];
__device__ float g_xpool[25088 * C];
__device__ float g_agg[MAXN * C2];
__device__ float g_feat[MAXN * C2];
__device__ float g_h1[MAXN * C];
__device__ float g_h2[MAXN * C];
__device__ float g_xd3[6272 * C];
__device__ float g_xu0[12544 * C];
__device__ float g_xu1[25088 * C];
__device__ int g_nmap[MAXN + 1];
__device__ int g_es[3 * MAXE];
__device__ int g_er[3 * MAXE];
__device__ int g_ecnt[4];
__device__ int g_col[4 * 2 * MAXE];
__device__ int g_rowptr[4 * (MAXN + 2)];
__device__ int g_deg[MAXN + 1];
__device__ int g_cursor[MAXN + 1];

// ------------------------------------------------------------------ helpers
__device__ __forceinline__ float warp_sum(float v) {
    #pragma unroll
    for (int o = 16; o; o >>= 1) v += __shfl_xor_sync(0xffffffffu, v, o);
    return v;
}

__device__ __forceinline__ float gelu_exact(float v) {
    return 0.5f * v * (1.0f + erff(v * 0.70710678118654752f));
}

__device__ __forceinline__ void ffma2(unsigned long long& d,
                                      unsigned long long a,
                                      unsigned long long b) {
    asm("fma.rn.f32x2 %0, %1, %2, %0;" : "+l"(d) : "l"(a), "l"(b));
}

// ------------------------------------------------------------------ scoring
__global__ void k_score(const float* __restrict__ x, const float* __restrict__ w, int nn) {
    int wid  = (blockIdx.x * blockDim.x + threadIdx.x) >> 5;
    int lane = threadIdx.x & 31;
    if (wid >= nn) return;
    float4 wv = *(const float4*)(w + lane * 4);
    float4 xv = *(const float4*)(x + (size_t)wid * C + lane * 4);
    float dot = xv.x * wv.x + xv.y * wv.y + xv.z * wv.z + xv.w * wv.w;
    float nrm = wv.x * wv.x + wv.y * wv.y + wv.z * wv.z + wv.w * wv.w;
    dot = warp_sum(dot);
    nrm = warp_sum(nrm);
    if (lane == 0) g_score[wid] = tanhf(dot / sqrtf(nrm));
}

// ------------------------------------------------------------------ top-k sort
__global__ void k_keyinit(int nn, int P) {
    int i = blockIdx.x * blockDim.x + threadIdx.x;
    if (i >= P) return;
    unsigned long long kk;
    if (i < nn) {
        unsigned u = __float_as_uint(g_score[i]);
        u = (u & 0x80000000u) ? ~u : (u | 0x80000000u);
        kk = (((unsigned long long)(~u)) << 32) | (unsigned)i;
    } else {
        kk = 0xFFFFFFFFFFFFFFFFULL;
    }
    g_keys[i] = kk;
}

__global__ void k_sort_local_full() {
    __shared__ unsigned long long sk[SCHUNK];
    int base = blockIdx.x * SCHUNK;
    int t = threadIdx.x;
    sk[t] = g_keys[base + t];
    sk[t + 1024] = g_keys[base + t + 1024];
    __syncthreads();
    for (int k = 2; k <= SCHUNK; k <<= 1) {
        for (int j = k >> 1; j > 0; j >>= 1) {
            int i = ((t & ~(j - 1)) << 1) | (t & (j - 1));
            int l = i | j;
            bool up = (((base + i) & k) == 0);
            unsigned long long a = sk[i], b = sk[l];
            if ((a > b) == up) { sk[i] = b; sk[l] = a; }
            __syncthreads();
        }
    }
    g_keys[base + t] = sk[t];
    g_keys[base + t + 1024] = sk[t + 1024];
}

__global__ void k_sort_global(int j, int k, int P) {
    int t = blockIdx.x * blockDim.x + threadIdx.x;
    if (t >= (P >> 1)) return;
    int i = ((t & ~(j - 1)) << 1) | (t & (j - 1));
    int l = i | j;
    bool up = ((i & k) == 0);
    unsigned long long a = g_keys[i], b = g_keys[l];
    if ((a > b) == up) { g_keys[i] = b; g_keys[l] = a; }
}

__global__ void k_sort_local_merge(int k) {
    __shared__ unsigned long long sk[SCHUNK];
    int base = blockIdx.x * SCHUNK;
    int t = threadIdx.x;
    sk[t] = g_keys[base + t];
    sk[t + 1024] = g_keys[base + t + 1024];
    __syncthreads();
    bool up = ((base & k) == 0);
    for (int j = SCHUNK >> 1; j > 0; j >>= 1) {
        int i = ((t & ~(j - 1)) << 1) | (t & (j - 1));
        int l = i | j;
        unsigned long long a = sk[i], b = sk[l];
        if ((a > b) == up) { sk[i] = b; sk[l] = a; }
        __syncthreads();
    }
    g_keys[base + t] = sk[t];
    g_keys[base + t + 1024] = sk[t + 1024];
}

// ------------------------------------------------------------------ pooling
__global__ void k_pool(const float* __restrict__ xin, int* __restrict__ perm,
                       float* __restrict__ xout, int kk) {
    int wid  = (blockIdx.x * blockDim.x + threadIdx.x) >> 5;
    int lane = threadIdx.x & 31;
    if (wid >= kk) return;
    int p = (int)(g_keys[wid] & 0xFFFFFFFFULL);
    float val = g_score[p];
    if (lane == 0) perm[wid] = p;
    float4 v = *(const float4*)(xin + (size_t)p * C + lane * 4);
    v.x *= val; v.y *= val; v.z *= val; v.w *= val;
    *(float4*)(xout + (size_t)wid * C + lane * 4) = v;
}

__global__ void k_seti(int* ptr, int cnt, int val) {
    int i = blockIdx.x * blockDim.x + threadIdx.x;
    if (i < cnt) ptr[i] = val;
}

__global__ void k_nmap_scatter(const int* __restrict__ perm, int kk) {
    int i = blockIdx.x * blockDim.x + threadIdx.x;
    if (i < kk) g_nmap[perm[i]] = i;
}

// warp-aggregated stream compaction
__global__ void k_remap(const int* __restrict__ sin, const int* __restrict__ rin,
                        int cntConst, const int* cntDev, int kk,
                        int* __restrict__ sout, int* __restrict__ rout, int* cntOut) {
    int e = blockIdx.x * blockDim.x + threadIdx.x;
    int cnt = cntDev ? __ldg(cntDev) : cntConst;
    bool valid = false;
    int ns = 0, nr = 0;
    if (e < cnt) {
        ns = g_nmap[sin[e]];
        nr = g_nmap[rin[e]];
        valid = (ns < kk) && (nr < kk);
    }
    unsigned mask = __ballot_sync(0xffffffffu, valid);
    if (!valid) return;
    int lane = threadIdx.x & 31;
    int leader = __ffs(mask) - 1;
    int rank = __popc(mask & ((1u << lane) - 1));
    int base = 0;
    if (lane == leader) base = atomicAdd(cntOut, __popc(mask));
    base = __shfl_sync(mask, base, leader);
    sout[base + rank] = ns;
    rout[base + rank] = nr;
}

// ------------------------------------------------------------------ CSR build
__global__ void k_hist(const int* __restrict__ s, const int* __restrict__ r,
                       int cntConst, const int* cntDev) {
    int e = blockIdx.x * blockDim.x + threadIdx.x;
    int cnt = cntDev ? __ldg(cntDev) : cntConst;
    if (e >= cnt) return;
    atomicAdd(&g_deg[r[e]], 1);
    atomicAdd(&g_deg[s[e]], 1);
}

__global__ void k_scan(int nn, int* __restrict__ rowptr) {
    __shared__ int warpsum[32];
    __shared__ int carry;
    int t = threadIdx.x, lane = t & 31, wid = t >> 5;
    if (t == 0) { rowptr[0] = 0; carry = 0; }
    __syncthreads();
    for (int base = 0; base < nn; base += 1024) {
        int v = (base + t < nn) ? g_deg[base + t] : 0;
        int x = v;
        #pragma unroll
        for (int o = 1; o < 32; o <<= 1) {
            int y = __shfl_up_sync(0xffffffffu, x, o);
            if (lane >= o) x += y;
        }
        if (lane == 31) warpsum[wid] = x;
        __syncthreads();
        if (wid == 0) {
            int s = warpsum[lane];
            #pragma unroll
            for (int o = 1; o < 32; o <<= 1) {
                int y = __shfl_up_sync(0xffffffffu, s, o);
                if (lane >= o) s += y;
            }
            warpsum[lane] = s;
        }
        __syncthreads();
        int off = carry + (wid ? warpsum[wid - 1] : 0);
        if (base + t < nn) rowptr[base + t + 1] = off + x;
        int total = warpsum[31];
        __syncthreads();
        if (t == 0) carry += total;
        __syncthreads();
    }
    for (int i = t; i <= nn; i += 1024) g_cursor[i] = rowptr[i];
}

__global__ void k_fill(const int* __restrict__ s, const int* __restrict__ r,
                       int cntConst, const int* cntDev, int* __restrict__ col) {
    int e = blockIdx.x * blockDim.x + threadIdx.x;
    int cnt = cntDev ? __ldg(cntDev) : cntConst;
    if (e >= cnt) return;
    int se = s[e], re = r[e];
    int p1 = atomicAdd(&g_cursor[re], 1); col[p1] = se;
    int p2 = atomicAdd(&g_cursor[se], 1); col[p2] = re;
}

// ------------------------------------------------------------------ aggregation (gather CSR)
template <int CH>
__global__ void k_agg(const int* __restrict__ rowptr, const int* __restrict__ colv,
                      const float* __restrict__ x, float* __restrict__ out, int nn) {
    int w    = (blockIdx.x * blockDim.x + threadIdx.x) >> 5;
    int lane = threadIdx.x & 31;
    if (w >= nn) return;
    int beg = rowptr[w], end = rowptr[w + 1];
    const int F = CH / 32;
    float acc[F];
    #pragma unroll
    for (int i = 0; i < F; i++) acc[i] = 0.f;
    for (int e = beg; e < end; e++) {
        int u = __ldg(colv + e);
        const float4* p = (const float4*)(x + (size_t)u * CH + lane * F);
        #pragma unroll
        for (int q = 0; q < F / 4; q++) {
            float4 v = __ldg(p + q);
            acc[4 * q + 0] += v.x;
            acc[4 * q + 1] += v.y;
            acc[4 * q + 2] += v.z;
            acc[4 * q + 3] += v.w;
        }
    }
    float4* o = (float4*)(out + (size_t)w * CH + lane * F);
    #pragma unroll
    for (int q = 0; q < F / 4; q++)
        o[q] = make_float4(acc[4 * q], acc[4 * q + 1], acc[4 * q + 2], acc[4 * q + 3]);
}

// ------------------------------------------------------------------ GEMM (M x K @ K x 128 + bias [+gelu])
// f32x2 packed FMA, 128x128 tile, KT=16, double-buffered smem.
// Rows packed pairwise in accumulator halves; Bs duplicated in quarter layout
// so all LDS are conflict-free (As is broadcast).
template <int ACT>
__global__ __launch_bounds__(256, 2) void k_gemm(const float* __restrict__ A,
                                                 const float* __restrict__ W,
                                                 const float* __restrict__ bias,
                                                 float* __restrict__ out, int M, int K) {
    __shared__ float As[2][16][128];        // [buf][kk][m]
    __shared__ float Bs[2][16][4][64];      // [buf][kk][q][tx*4+e]  (duplicated pairs)
    const int tid = threadIdx.x;
    const int row0 = blockIdx.x * 128;
    const int tx = tid & 15, ty = tid >> 4;

    // A staging: thread loads 8 floats of one row
    const int ar = tid >> 1;
    const int ac = (tid & 1) * 8;
    // W staging: thread loads rows wr, wr+8, 4 cols each
    const int wr = tid >> 5;
    const int wc = (tid & 31) * 4;
    const int wtx = wc >> 3;
    const int wq = (wc & 7) >> 1;    // 0 or 2

    const int nt = K >> 4;
    const int arow = row0 + ar;
    const bool aval = (arow < M);
    const float* Aptr = A + (size_t)(aval ? arow : 0) * K + ac;

    unsigned long long acc[4][8];
    #pragma unroll
    for (int p = 0; p < 4; p++)
        #pragma unroll
        for (int j = 0; j < 8; j++) acc[p][j] = 0ULL;

    float4 a0, a1, w0, w1;
    if (aval) { a0 = *(const float4*)(Aptr); a1 = *(const float4*)(Aptr + 4); }
    else { a0 = make_float4(0.f, 0.f, 0.f, 0.f); a1 = a0; }
    w0 = *(const float4*)(W + (size_t)wr * 128 + wc);
    w1 = *(const float4*)(W + (size_t)(wr + 8) * 128 + wc);

    As[0][ac + 0][ar] = a0.x; As[0][ac + 1][ar] = a0.y;
    As[0][ac + 2][ar] = a0.z; As[0][ac + 3][ar] = a0.w;
    As[0][ac + 4][ar] = a1.x; As[0][ac + 5][ar] = a1.y;
    As[0][ac + 6][ar] = a1.z; As[0][ac + 7][ar] = a1.w;
    *(float4*)&Bs[0][wr][wq][wtx * 4]       = make_float4(w0.x, w0.x, w0.y, w0.y);
    *(float4*)&Bs[0][wr][wq + 1][wtx * 4]   = make_float4(w0.z, w0.z, w0.w, w0.w);
    *(float4*)&Bs[0][wr + 8][wq][wtx * 4]     = make_float4(w1.x, w1.x, w1.y, w1.y);
    *(float4*)&Bs[0][wr + 8][wq + 1][wtx * 4] = make_float4(w1.z, w1.z, w1.w, w1.w);
    __syncthreads();

    for (int t = 0; t < nt; t++) {
        const int cur = t & 1;
        if (t + 1 < nt) {
            int k0 = (t + 1) * 16;
            if (aval) { a0 = *(const float4*)(Aptr + k0); a1 = *(const float4*)(Aptr + k0 + 4); }
            w0 = *(const float4*)(W + (size_t)(k0 + wr) * 128 + wc);
            w1 = *(const float4*)(W + (size_t)(k0 + wr + 8) * 128 + wc);
        }
        #pragma unroll
        for (int kk = 0; kk < 16; kk++) {
            ulonglong2 av0 = *(const ulonglong2*)&As[cur][kk][ty * 8];
            ulonglong2 av1 = *(const ulonglong2*)&As[cur][kk][ty * 8 + 4];
            unsigned long long a2[4] = {av0.x, av0.y, av1.x, av1.y};
            unsigned long long b2[8];
            #pragma unroll
            for (int q = 0; q < 4; q++) {
                ulonglong2 bv = *(const ulonglong2*)&Bs[cur][kk][q][tx * 4];
                b2[2 * q] = bv.x;
                b2[2 * q + 1] = bv.y;
            }
            #pragma unroll
            for (int p = 0; p < 4; p++)
                #pragma unroll
                for (int j = 0; j < 8; j++) ffma2(acc[p][j], a2[p], b2[j]);
        }
        if (t + 1 < nt) {
            const int nb = 1 - cur;
            As[nb][ac + 0][ar] = a0.x; As[nb][ac + 1][ar] = a0.y;
            As[nb][ac + 2][ar] = a0.z; As[nb][ac + 3][ar] = a0.w;
            As[nb][ac + 4][ar] = a1.x; As[nb][ac + 5][ar] = a1.y;
            As[nb][ac + 6][ar] = a1.z; As[nb][ac + 7][ar] = a1.w;
            *(float4*)&Bs[nb][wr][wq][wtx * 4]       = make_float4(w0.x, w0.x, w0.y, w0.y);
            *(float4*)&Bs[nb][wr][wq + 1][wtx * 4]   = make_float4(w0.z, w0.z, w0.w, w0.w);
            *(float4*)&Bs[nb][wr + 8][wq][wtx * 4]     = make_float4(w1.x, w1.x, w1.y, w1.y);
            *(float4*)&Bs[nb][wr + 8][wq + 1][wtx * 4] = make_float4(w1.z, w1.z, w1.w, w1.w);
            __syncthreads();
        }
    }

    float bvv[8];
    *(float4*)&bvv[0] = *(const float4*)(bias + tx * 8);
    *(float4*)&bvv[4] = *(const float4*)(bias + tx * 8 + 4);
    #pragma unroll
    for (int p = 0; p < 4; p++) {
        int r0 = row0 + ty * 8 + 2 * p;
        float o0[8], o1[8];
        #pragma unroll
        for (int j = 0; j < 8; j++) {
            float2 u = *(float2*)&acc[p][j];
            float v0 = u.x + bvv[j];
            float v1 = u.y + bvv[j];
            if (ACT) { v0 = gelu_exact(v0); v1 = gelu_exact(v1); }
            o0[j] = v0; o1[j] = v1;
        }
        if (r0 < M) {
            *(float4*)(out + (size_t)r0 * 128 + tx * 8)     = *(float4*)&o0[0];
            *(float4*)(out + (size_t)r0 * 128 + tx * 8 + 4) = *(float4*)&o0[4];
        }
        if (r0 + 1 < M) {
            *(float4*)(out + (size_t)(r0 + 1) * 128 + tx * 8)     = *(float4*)&o1[0];
            *(float4*)(out + (size_t)(r0 + 1) * 128 + tx * 8 + 4) = *(float4*)&o1[4];
        }
    }
}

// ------------------------------------------------------------------ LayerNorm
__global__ void k_ln(const float* __restrict__ h, const float* __restrict__ g,
                     const float* __restrict__ b, float* __restrict__ out, int M) {
    int w    = (blockIdx.x * blockDim.x + threadIdx.x) >> 5;
    int lane = threadIdx.x & 31;
    if (w >= M) return;
    float4 v = *(const float4*)(h + (size_t)w * C + lane * 4);
    float s = warp_sum(v.x + v.y + v.z + v.w);
    float mu = s * (1.0f / 128.0f);
    float dx = v.x - mu, dy = v.y - mu, dz = v.z - mu, dw = v.w - mu;
    float q = warp_sum(dx * dx + dy * dy + dz * dz + dw * dw);
    float rs = rsqrtf(q * (1.0f / 128.0f) + 1e-5f);
    float4 gv = *(const float4*)(g + lane * 4);
    float4 bv = *(const float4*)(b + lane * 4);
    float4 o;
    o.x = gv.x * dx * rs + bv.x;
    o.y = gv.y * dy * rs + bv.y;
    o.z = gv.z * dz * rs + bv.z;
    o.w = gv.w * dw * rs + bv.w;
    *(float4*)(out + (size_t)w * C + lane * 4) = o;
}

// ------------------------------------------------------------------ up-path feature build
__global__ void k_featcopy(const float* __restrict__ res, int nn) {
    int w    = (blockIdx.x * blockDim.x + threadIdx.x) >> 5;
    int lane = threadIdx.x & 31;
    if (w >= nn) return;
    float4 v = *(const float4*)(res + (size_t)w * C + lane * 4);
    *(float4*)(g_feat + (size_t)w * C2 + lane * 4) = v;
    *(float4*)(g_feat + (size_t)w * C2 + C + lane * 4) = make_float4(0.f, 0.f, 0.f, 0.f);
}

__global__ void k_featscatter(const int* __restrict__ perm, const float* __restrict__ xc, int kk) {
    int w    = (blockIdx.x * blockDim.x + threadIdx.x) >> 5;
    int lane = threadIdx.x & 31;
    if (w >= kk) return;
    int p = perm[w];
    float4 v = *(const float4*)(xc + (size_t)w * C + lane * 4);
    *(float4*)(g_feat + (size_t)p * C2 + C + lane * 4) = v;
}

// ------------------------------------------------------------------ host
static inline int divup(int a, int b) { return (a + b - 1) / b; }

extern "C" void kernel_launch(void* const* d_in, const int* in_sizes, int n_in,
                              void* d_out, int out_size) {
    const float* x0  = (const float*)d_in[0];
    const int*   s0  = (const int*)d_in[1];
    const int*   r0  = (const int*)d_in[2];
    const float* pw  = (const float*)d_in[3];
    const float* dW1 = (const float*)d_in[4];
    const float* db1 = (const float*)d_in[5];
    const float* dW2 = (const float*)d_in[6];
    const float* db2 = (const float*)d_in[7];
    const float* dW3 = (const float*)d_in[8];
    const float* db3 = (const float*)d_in[9];
    const float* dg  = (const float*)d_in[10];
    const float* dbt = (const float*)d_in[11];
    const float* uW1 = (const float*)d_in[12];
    const float* ub1 = (const float*)d_in[13];
    const float* uW2 = (const float*)d_in[14];
    const float* ub2 = (const float*)d_in[15];
    const float* uW3 = (const float*)d_in[16];
    const float* ub3 = (const float*)d_in[17];
    const float* ug  = (const float*)d_in[18];
    const float* ubt = (const float*)d_in[19];

    int N = in_sizes[0] / C;
    int E = in_sizes[1];
    int n[4];
    n[0] = N;
    for (int i = 0; i < 3; i++) n[i + 1] = (n[i] + 1) / 2;

    void* p;
    float *xs1, *xs2, *xpool, *agg, *feat, *h1, *h2, *xd3, *xu0, *xu1;
    int *permbuf, *nmap, *es, *er, *ecnt, *col, *rowptr, *deg;
    cudaGetSymbolAddress(&p, g_xs1);     xs1 = (float*)p;
    cudaGetSymbolAddress(&p, g_xs2);     xs2 = (float*)p;
    cudaGetSymbolAddress(&p, g_xpool);   xpool = (float*)p;
    cudaGetSymbolAddress(&p, g_agg);     agg = (float*)p;
    cudaGetSymbolAddress(&p, g_feat);    feat = (float*)p;
    cudaGetSymbolAddress(&p, g_h1);      h1 = (float*)p;
    cudaGetSymbolAddress(&p, g_h2);      h2 = (float*)p;
    cudaGetSymbolAddress(&p, g_xd3);     xd3 = (float*)p;
    cudaGetSymbolAddress(&p, g_xu0);     xu0 = (float*)p;
    cudaGetSymbolAddress(&p, g_xu1);     xu1 = (float*)p;
    cudaGetSymbolAddress(&p, g_permbuf); permbuf = (int*)p;
    cudaGetSymbolAddress(&p, g_nmap);    nmap = (int*)p;
    cudaGetSymbolAddress(&p, g_es);      es = (int*)p;
    cudaGetSymbolAddress(&p, g_er);      er = (int*)p;
    cudaGetSymbolAddress(&p, g_ecnt);    ecnt = (int*)p;
    cudaGetSymbolAddress(&p, g_col);     col = (int*)p;
    cudaGetSymbolAddress(&p, g_rowptr);  rowptr = (int*)p;
    cudaGetSymbolAddress(&p, g_deg);     deg = (int*)p;

    int egrid = divup(E, TPB);

    auto build_csr = [&](int set, const int* s, const int* r, int cntConst,
                         const int* cntDev, int nn) {
        int* rp = rowptr + set * (MAXN + 2);
        int* cl = col + (size_t)set * 2 * MAXE;
        k_seti<<<divup(nn + 1, TPB), TPB>>>(deg, nn + 1, 0);
        k_hist<<<egrid, TPB>>>(s, r, cntConst, cntDev);
        k_scan<<<1, 1024>>>(nn, rp);
        k_fill<<<egrid, TPB>>>(s, r, cntConst, cntDev, cl);
    };

    int poff[3] = {0, n[1], n[1] + n[2]};

    build_csr(0, s0, r0, E, nullptr, N);

    // -------------------------------------------------- down path
    const float* xin = x0;
    float* xsbuf[3] = {xs1, xs2, xd3};
    for (int i = 0; i < 3; i++) {
        int nn = n[i], kk = n[i + 1];
        int P = 1;
        while (P < nn) P <<= 1;

        k_score<<<divup(nn, 8), TPB>>>(xin, pw + i * C, nn);
        k_keyinit<<<divup(P, TPB), TPB>>>(nn, P);
        k_sort_local_full<<<P / SCHUNK, 1024>>>();
        for (int k2 = SCHUNK * 2; k2 <= P; k2 <<= 1) {
            for (int j = k2 >> 1; j >= SCHUNK; j >>= 1)
                k_sort_global<<<divup(P / 2, TPB), TPB>>>(j, k2, P);
            k_sort_local_merge<<<P / SCHUNK, 1024>>>(k2);
        }

        int* perm = permbuf + poff[i];
        k_pool<<<divup(kk, 8), TPB>>>(xin, perm, xpool, kk);

        k_seti<<<divup(nn + 1, TPB), TPB>>>(nmap, nn + 1, kk);
        k_nmap_scatter<<<divup(kk, TPB), TPB>>>(perm, kk);
        k_seti<<<1, 32>>>(ecnt + i, 1, 0);
        const int* sin = (i == 0) ? s0 : (es + (i - 1) * MAXE);
        const int* rin = (i == 0) ? r0 : (er + (i - 1) * MAXE);
        const int* cd  = (i == 0) ? nullptr : (ecnt + (i - 1));
        k_remap<<<egrid, TPB>>>(sin, rin, (i == 0) ? E : 0, cd, kk,
                                es + i * MAXE, er + i * MAXE, ecnt + i);

        build_csr(i + 1, es + i * MAXE, er + i * MAXE, 0, ecnt + i, kk);

        k_agg<128><<<divup(kk, 8), TPB>>>(rowptr + (i + 1) * (MAXN + 2),
                                          col + (size_t)(i + 1) * 2 * MAXE, xpool, agg, kk);
        k_gemm<1><<<divup(kk, 128), 256>>>(agg, dW1 + i * C * C, db1 + i * C, h1, kk, C);
        k_gemm<1><<<divup(kk, 128), 256>>>(h1, dW2 + i * C * C, db2 + i * C, h2, kk, C);
        k_gemm<0><<<divup(kk, 128), 256>>>(h2, dW3 + i * C * C, db3 + i * C, h1, kk, C);
        k_ln<<<divup(kk, 8), TPB>>>(h1, dg + i * C, dbt + i * C, xsbuf[i], kk);

        xin = xsbuf[i];
    }

    // -------------------------------------------------- up path
    const float* xcur = xd3;
    for (int i = 0; i < 3; i++) {
        int j = 2 - i;
        int nn = n[j];
        int kk = n[j + 1];
        const float* res = (j == 0) ? x0 : ((j == 1) ? xs1 : xs2);
        const int* perm = permbuf + poff[j];

        k_featcopy<<<divup(nn, 8), TPB>>>(res, nn);
        k_featscatter<<<divup(kk, 8), TPB>>>(perm, xcur, kk);

        k_agg<256><<<divup(nn, 8), TPB>>>(rowptr + j * (MAXN + 2),
                                          col + (size_t)j * 2 * MAXE, feat, agg, nn);
        k_gemm<1><<<divup(nn, 128), 256>>>(agg, uW1 + i * C2 * C, ub1 + i * C, h1, nn, C2);
        k_gemm<1><<<divup(nn, 128), 256>>>(h1, uW2 + i * C * C, ub2 + i * C, h2, nn, C);
        k_gemm<0><<<divup(nn, 128), 256>>>(h2, uW3 + i * C * C, ub3 + i * C, h1, nn, C);

        float* outp = (i == 2) ? (float*)d_out : ((i == 0) ? xu0 : xu1);
        k_ln<<<divup(nn, 8), TPB>>>(h1, ug + i * C, ubt + i * C, outp, nn);
        xcur = outp;
    }
}

// round 15
// speedup vs baseline: 1.0823x; 1.0005x over previous
#include <cuda_runtime.h>
#include <math.h>

#define C    128
#define C2   256
#define MAXN 50000
#define MAXE 600000
#define PADMAX 65536
#define SCHUNK 2048
#define TPB  256

// ------------------------------------------------------------------ scratch
__device__ float g_score[MAXN];
__device__ unsigned long long g_keys[PADMAX];
__device__ int   g_permbuf[MAXN];
__device__ float g_xs1[25088 * C];
__device__ float g_xs2[12544 * C];
__device__ float g_xpool[25088 * C];
__device__ float g_agg[MAXN * C2];
__device__ float g_feat[MAXN * C2];
__device__ float g_h1[MAXN * C];
__device__ float g_h2[MAXN * C];
__device__ float g_xd3[6272 * C];
__device__ float g_xu0[12544 * C];
__device__ float g_xu1[25088 * C];
__device__ int g_nmap[MAXN + 1];
__device__ int g_es[3 * MAXE];
__device__ int g_er[3 * MAXE];
__device__ int g_ecnt[4];
__device__ int g_col[4 * 2 * MAXE];
__device__ int g_rowptr[4 * (MAXN + 2)];
__device__ int g_deg[MAXN + 1];
__device__ int g_cursor[MAXN + 1];

// ------------------------------------------------------------------ helpers
__device__ __forceinline__ float warp_sum(float v) {
    #pragma unroll
    for (int o = 16; o; o >>= 1) v += __shfl_xor_sync(0xffffffffu, v, o);
    return v;
}

__device__ __forceinline__ float gelu_exact(float v) {
    return 0.5f * v * (1.0f + erff(v * 0.70710678118654752f));
}

__device__ __forceinline__ void ffma2(unsigned long long& d,
                                      unsigned long long a,
                                      unsigned long long b) {
    asm("fma.rn.f32x2 %0, %1, %2, %0;" : "+l"(d) : "l"(a), "l"(b));
}

// ------------------------------------------------------------------ scoring
__global__ void k_score(const float* __restrict__ x, const float* __restrict__ w, int nn) {
    int wid  = (blockIdx.x * blockDim.x + threadIdx.x) >> 5;
    int lane = threadIdx.x & 31;
    if (wid >= nn) return;
    float4 wv = *(const float4*)(w + lane * 4);
    float4 xv = *(const float4*)(x + (size_t)wid * C + lane * 4);
    float dot = xv.x * wv.x + xv.y * wv.y + xv.z * wv.z + xv.w * wv.w;
    float nrm = wv.x * wv.x + wv.y * wv.y + wv.z * wv.z + wv.w * wv.w;
    dot = warp_sum(dot);
    nrm = warp_sum(nrm);
    if (lane == 0) g_score[wid] = tanhf(dot / sqrtf(nrm));
}

// ------------------------------------------------------------------ top-k sort
__global__ void k_keyinit(int nn, int P) {
    int i = blockIdx.x * blockDim.x + threadIdx.x;
    if (i >= P) return;
    unsigned long long kk;
    if (i < nn) {
        unsigned u = __float_as_uint(g_score[i]);
        u = (u & 0x80000000u) ? ~u : (u | 0x80000000u);
        kk = (((unsigned long long)(~u)) << 32) | (unsigned)i;
    } else {
        kk = 0xFFFFFFFFFFFFFFFFULL;
    }
    g_keys[i] = kk;
}

__global__ void k_sort_local_full() {
    __shared__ unsigned long long sk[SCHUNK];
    int base = blockIdx.x * SCHUNK;
    int t = threadIdx.x;
    sk[t] = g_keys[base + t];
    sk[t + 1024] = g_keys[base + t + 1024];
    __syncthreads();
    for (int k = 2; k <= SCHUNK; k <<= 1) {
        for (int j = k >> 1; j > 0; j >>= 1) {
            int i = ((t & ~(j - 1)) << 1) | (t & (j - 1));
            int l = i | j;
            bool up = (((base + i) & k) == 0);
            unsigned long long a = sk[i], b = sk[l];
            if ((a > b) == up) { sk[i] = b; sk[l] = a; }
            __syncthreads();
        }
    }
    g_keys[base + t] = sk[t];
    g_keys[base + t + 1024] = sk[t + 1024];
}

__global__ void k_sort_global(int j, int k, int P) {
    int t = blockIdx.x * blockDim.x + threadIdx.x;
    if (t >= (P >> 1)) return;
    int i = ((t & ~(j - 1)) << 1) | (t & (j - 1));
    int l = i | j;
    bool up = ((i & k) == 0);
    unsigned long long a = g_keys[i], b = g_keys[l];
    if ((a > b) == up) { g_keys[i] = b; g_keys[l] = a; }
}

__global__ void k_sort_local_merge(int k) {
    __shared__ unsigned long long sk[SCHUNK];
    int base = blockIdx.x * SCHUNK;
    int t = threadIdx.x;
    sk[t] = g_keys[base + t];
    sk[t + 1024] = g_keys[base + t + 1024];
    __syncthreads();
    bool up = ((base & k) == 0);
    for (int j = SCHUNK >> 1; j > 0; j >>= 1) {
        int i = ((t & ~(j - 1)) << 1) | (t & (j - 1));
        int l = i | j;
        unsigned long long a = sk[i], b = sk[l];
        if ((a > b) == up) { sk[i] = b; sk[l] = a; }
        __syncthreads();
    }
    g_keys[base + t] = sk[t];
    g_keys[base + t + 1024] = sk[t + 1024];
}

// ------------------------------------------------------------------ pooling
__global__ void k_pool(const float* __restrict__ xin, int* __restrict__ perm,
                       float* __restrict__ xout, int kk) {
    int wid  = (blockIdx.x * blockDim.x + threadIdx.x) >> 5;
    int lane = threadIdx.x & 31;
    if (wid >= kk) return;
    int p = (int)(g_keys[wid] & 0xFFFFFFFFULL);
    float val = g_score[p];
    if (lane == 0) perm[wid] = p;
    float4 v = *(const float4*)(xin + (size_t)p * C + lane * 4);
    v.x *= val; v.y *= val; v.z *= val; v.w *= val;
    *(float4*)(xout + (size_t)wid * C + lane * 4) = v;
}

__global__ void k_seti(int* ptr, int cnt, int val) {
    int i = blockIdx.x * blockDim.x + threadIdx.x;
    if (i < cnt) ptr[i] = val;
}

__global__ void k_nmap_scatter(const int* __restrict__ perm, int kk) {
    int i = blockIdx.x * blockDim.x + threadIdx.x;
    if (i < kk) g_nmap[perm[i]] = i;
}

// warp-aggregated stream compaction
__global__ void k_remap(const int* __restrict__ sin, const int* __restrict__ rin,
                        int cntConst, const int* cntDev, int kk,
                        int* __restrict__ sout, int* __restrict__ rout, int* cntOut) {
    int e = blockIdx.x * blockDim.x + threadIdx.x;
    int cnt = cntDev ? __ldg(cntDev) : cntConst;
    bool valid = false;
    int ns = 0, nr = 0;
    if (e < cnt) {
        ns = g_nmap[sin[e]];
        nr = g_nmap[rin[e]];
        valid = (ns < kk) && (nr < kk);
    }
    unsigned mask = __ballot_sync(0xffffffffu, valid);
    if (!valid) return;
    int lane = threadIdx.x & 31;
    int leader = __ffs(mask) - 1;
    int rank = __popc(mask & ((1u << lane) - 1));
    int base = 0;
    if (lane == leader) base = atomicAdd(cntOut, __popc(mask));
    base = __shfl_sync(mask, base, leader);
    sout[base + rank] = ns;
    rout[base + rank] = nr;
}

// ------------------------------------------------------------------ CSR build
__global__ void k_hist(const int* __restrict__ s, const int* __restrict__ r,
                       int cntConst, const int* cntDev) {
    int e = blockIdx.x * blockDim.x + threadIdx.x;
    int cnt = cntDev ? __ldg(cntDev) : cntConst;
    if (e >= cnt) return;
    atomicAdd(&g_deg[r[e]], 1);
    atomicAdd(&g_deg[s[e]], 1);
}

__global__ void k_scan(int nn, int* __restrict__ rowptr) {
    __shared__ int warpsum[32];
    __shared__ int carry;
    int t = threadIdx.x, lane = t & 31, wid = t >> 5;
    if (t == 0) { rowptr[0] = 0; carry = 0; }
    __syncthreads();
    for (int base = 0; base < nn; base += 1024) {
        int v = (base + t < nn) ? g_deg[base + t] : 0;
        int x = v;
        #pragma unroll
        for (int o = 1; o < 32; o <<= 1) {
            int y = __shfl_up_sync(0xffffffffu, x, o);
            if (lane >= o) x += y;
        }
        if (lane == 31) warpsum[wid] = x;
        __syncthreads();
        if (wid == 0) {
            int s = warpsum[lane];
            #pragma unroll
            for (int o = 1; o < 32; o <<= 1) {
                int y = __shfl_up_sync(0xffffffffu, s, o);
                if (lane >= o) s += y;
            }
            warpsum[lane] = s;
        }
        __syncthreads();
        int off = carry + (wid ? warpsum[wid - 1] : 0);
        if (base + t < nn) rowptr[base + t + 1] = off + x;
        int total = warpsum[31];
        __syncthreads();
        if (t == 0) carry += total;
        __syncthreads();
    }
    for (int i = t; i <= nn; i += 1024) g_cursor[i] = rowptr[i];
}

__global__ void k_fill(const int* __restrict__ s, const int* __restrict__ r,
                       int cntConst, const int* cntDev, int* __restrict__ col) {
    int e = blockIdx.x * blockDim.x + threadIdx.x;
    int cnt = cntDev ? __ldg(cntDev) : cntConst;
    if (e >= cnt) return;
    int se = s[e], re = r[e];
    int p1 = atomicAdd(&g_cursor[re], 1); col[p1] = se;
    int p2 = atomicAdd(&g_cursor[se], 1); col[p2] = re;
}

// ------------------------------------------------------------------ aggregation (gather CSR)
template <int CH>
__global__ void k_agg(const int* __restrict__ rowptr, const int* __restrict__ colv,
                      const float* __restrict__ x, float* __restrict__ out, int nn) {
    int w    = (blockIdx.x * blockDim.x + threadIdx.x) >> 5;
    int lane = threadIdx.x & 31;
    if (w >= nn) return;
    int beg = rowptr[w], end = rowptr[w + 1];
    const int F = CH / 32;
    float acc[F];
    #pragma unroll
    for (int i = 0; i < F; i++) acc[i] = 0.f;
    for (int e = beg; e < end; e++) {
        int u = __ldg(colv + e);
        const float4* p = (const float4*)(x + (size_t)u * CH + lane * F);
        #pragma unroll
        for (int q = 0; q < F / 4; q++) {
            float4 v = __ldg(p + q);
            acc[4 * q + 0] += v.x;
            acc[4 * q + 1] += v.y;
            acc[4 * q + 2] += v.z;
            acc[4 * q + 3] += v.w;
        }
    }
    float4* o = (float4*)(out + (size_t)w * CH + lane * F);
    #pragma unroll
    for (int q = 0; q < F / 4; q++)
        o[q] = make_float4(acc[4 * q], acc[4 * q + 1], acc[4 * q + 2], acc[4 * q + 3]);
}

// ------------------------------------------------------------------ GEMM (M x K @ K x 128 + bias [+gelu])
// f32x2 packed FMA, 128x128 tile, KT=16, double-buffered smem.
// Rows packed pairwise in accumulator halves; Bs duplicated in quarter layout
// so all LDS are conflict-free (As is broadcast).
template <int ACT>
__global__ __launch_bounds__(256, 2) void k_gemm(const float* __restrict__ A,
                                                 const float* __restrict__ W,
                                                 const float* __restrict__ bias,
                                                 float* __restrict__ out, int M, int K) {
    __shared__ float As[2][16][128];        // [buf][kk][m]
    __shared__ float Bs[2][16][4][64];      // [buf][kk][q][tx*4+e]  (duplicated pairs)
    const int tid = threadIdx.x;
    const int row0 = blockIdx.x * 128;
    const int tx = tid & 15, ty = tid >> 4;

    // A staging: thread loads 8 floats of one row
    const int ar = tid >> 1;
    const int ac = (tid & 1) * 8;
    // W staging: thread loads rows wr, wr+8, 4 cols each
    const int wr = tid >> 5;
    const int wc = (tid & 31) * 4;
    const int wtx = wc >> 3;
    const int wq = (wc & 7) >> 1;    // 0 or 2

    const int nt = K >> 4;
    const int arow = row0 + ar;
    const bool aval = (arow < M);
    const float* Aptr = A + (size_t)(aval ? arow : 0) * K + ac;

    unsigned long long acc[4][8];
    #pragma unroll
    for (int p = 0; p < 4; p++)
        #pragma unroll
        for (int j = 0; j < 8; j++) acc[p][j] = 0ULL;

    float4 a0, a1, w0, w1;
    if (aval) { a0 = *(const float4*)(Aptr); a1 = *(const float4*)(Aptr + 4); }
    else { a0 = make_float4(0.f, 0.f, 0.f, 0.f); a1 = a0; }
    w0 = *(const float4*)(W + (size_t)wr * 128 + wc);
    w1 = *(const float4*)(W + (size_t)(wr + 8) * 128 + wc);

    As[0][ac + 0][ar] = a0.x; As[0][ac + 1][ar] = a0.y;
    As[0][ac + 2][ar] = a0.z; As[0][ac + 3][ar] = a0.w;
    As[0][ac + 4][ar] = a1.x; As[0][ac + 5][ar] = a1.y;
    As[0][ac + 6][ar] = a1.z; As[0][ac + 7][ar] = a1.w;
    *(float4*)&Bs[0][wr][wq][wtx * 4]       = make_float4(w0.x, w0.x, w0.y, w0.y);
    *(float4*)&Bs[0][wr][wq + 1][wtx * 4]   = make_float4(w0.z, w0.z, w0.w, w0.w);
    *(float4*)&Bs[0][wr + 8][wq][wtx * 4]     = make_float4(w1.x, w1.x, w1.y, w1.y);
    *(float4*)&Bs[0][wr + 8][wq + 1][wtx * 4] = make_float4(w1.z, w1.z, w1.w, w1.w);
    __syncthreads();

    for (int t = 0; t < nt; t++) {
        const int cur = t & 1;
        if (t + 1 < nt) {
            int k0 = (t + 1) * 16;
            if (aval) { a0 = *(const float4*)(Aptr + k0); a1 = *(const float4*)(Aptr + k0 + 4); }
            w0 = *(const float4*)(W + (size_t)(k0 + wr) * 128 + wc);
            w1 = *(const float4*)(W + (size_t)(k0 + wr + 8) * 128 + wc);
        }
        #pragma unroll
        for (int kk = 0; kk < 16; kk++) {
            ulonglong2 av0 = *(const ulonglong2*)&As[cur][kk][ty * 8];
            ulonglong2 av1 = *(const ulonglong2*)&As[cur][kk][ty * 8 + 4];
            unsigned long long a2[4] = {av0.x, av0.y, av1.x, av1.y};
            unsigned long long b2[8];
            #pragma unroll
            for (int q = 0; q < 4; q++) {
                ulonglong2 bv = *(const ulonglong2*)&Bs[cur][kk][q][tx * 4];
                b2[2 * q] = bv.x;
                b2[2 * q + 1] = bv.y;
            }
            #pragma unroll
            for (int p = 0; p < 4; p++)
                #pragma unroll
                for (int j = 0; j < 8; j++) ffma2(acc[p][j], a2[p], b2[j]);
        }
        if (t + 1 < nt) {
            const int nb = 1 - cur;
            As[nb][ac + 0][ar] = a0.x; As[nb][ac + 1][ar] = a0.y;
            As[nb][ac + 2][ar] = a0.z; As[nb][ac + 3][ar] = a0.w;
            As[nb][ac + 4][ar] = a1.x; As[nb][ac + 5][ar] = a1.y;
            As[nb][ac + 6][ar] = a1.z; As[nb][ac + 7][ar] = a1.w;
            *(float4*)&Bs[nb][wr][wq][wtx * 4]       = make_float4(w0.x, w0.x, w0.y, w0.y);
            *(float4*)&Bs[nb][wr][wq + 1][wtx * 4]   = make_float4(w0.z, w0.z, w0.w, w0.w);
            *(float4*)&Bs[nb][wr + 8][wq][wtx * 4]     = make_float4(w1.x, w1.x, w1.y, w1.y);
            *(float4*)&Bs[nb][wr + 8][wq + 1][wtx * 4] = make_float4(w1.z, w1.z, w1.w, w1.w);
            __syncthreads();
        }
    }

    float bvv[8];
    *(float4*)&bvv[0] = *(const float4*)(bias + tx * 8);
    *(float4*)&bvv[4] = *(const float4*)(bias + tx * 8 + 4);
    #pragma unroll
    for (int p = 0; p < 4; p++) {
        int r0 = row0 + ty * 8 + 2 * p;
        float o0[8], o1[8];
        #pragma unroll
        for (int j = 0; j < 8; j++) {
            float2 u = *(float2*)&acc[p][j];
            float v0 = u.x + bvv[j];
            float v1 = u.y + bvv[j];
            if (ACT) { v0 = gelu_exact(v0); v1 = gelu_exact(v1); }
            o0[j] = v0; o1[j] = v1;
        }
        if (r0 < M) {
            *(float4*)(out + (size_t)r0 * 128 + tx * 8)     = *(float4*)&o0[0];
            *(float4*)(out + (size_t)r0 * 128 + tx * 8 + 4) = *(float4*)&o0[4];
        }
        if (r0 + 1 < M) {
            *(float4*)(out + (size_t)(r0 + 1) * 128 + tx * 8)     = *(float4*)&o1[0];
            *(float4*)(out + (size_t)(r0 + 1) * 128 + tx * 8 + 4) = *(float4*)&o1[4];
        }
    }
}

// ------------------------------------------------------------------ LayerNorm
__global__ void k_ln(const float* __restrict__ h, const float* __restrict__ g,
                     const float* __restrict__ b, float* __restrict__ out, int M) {
    int w    = (blockIdx.x * blockDim.x + threadIdx.x) >> 5;
    int lane = threadIdx.x & 31;
    if (w >= M) return;
    float4 v = *(const float4*)(h + (size_t)w * C + lane * 4);
    float s = warp_sum(v.x + v.y + v.z + v.w);
    float mu = s * (1.0f / 128.0f);
    float dx = v.x - mu, dy = v.y - mu, dz = v.z - mu, dw = v.w - mu;
    float q = warp_sum(dx * dx + dy * dy + dz * dz + dw * dw);
    float rs = rsqrtf(q * (1.0f / 128.0f) + 1e-5f);
    float4 gv = *(const float4*)(g + lane * 4);
    float4 bv = *(const float4*)(b + lane * 4);
    float4 o;
    o.x = gv.x * dx * rs + bv.x;
    o.y = gv.y * dy * rs + bv.y;
    o.z = gv.z * dz * rs + bv.z;
    o.w = gv.w * dw * rs + bv.w;
    *(float4*)(out + (size_t)w * C + lane * 4) = o;
}

// ------------------------------------------------------------------ up-path feature build
__global__ void k_featcopy(const float* __restrict__ res, int nn) {
    int w    = (blockIdx.x * blockDim.x + threadIdx.x) >> 5;
    int lane = threadIdx.x & 31;
    if (w >= nn) return;
    float4 v = *(const float4*)(res + (size_t)w * C + lane * 4);
    *(float4*)(g_feat + (size_t)w * C2 + lane * 4) = v;
    *(float4*)(g_feat + (size_t)w * C2 + C + lane * 4) = make_float4(0.f, 0.f, 0.f, 0.f);
}

__global__ void k_featscatter(const int* __restrict__ perm, const float* __restrict__ xc, int kk) {
    int w    = (blockIdx.x * blockDim.x + threadIdx.x) >> 5;
    int lane = threadIdx.x & 31;
    if (w >= kk) return;
    int p = perm[w];
    float4 v = *(const float4*)(xc + (size_t)w * C + lane * 4);
    *(float4*)(g_feat + (size_t)p * C2 + C + lane * 4) = v;
}

// ------------------------------------------------------------------ host
static inline int divup(int a, int b) { return (a + b - 1) / b; }

extern "C" void kernel_launch(void* const* d_in, const int* in_sizes, int n_in,
                              void* d_out, int out_size) {
    const float* x0  = (const float*)d_in[0];
    const int*   s0  = (const int*)d_in[1];
    const int*   r0  = (const int*)d_in[2];
    const float* pw  = (const float*)d_in[3];
    const float* dW1 = (const float*)d_in[4];
    const float* db1 = (const float*)d_in[5];
    const float* dW2 = (const float*)d_in[6];
    const float* db2 = (const float*)d_in[7];
    const float* dW3 = (const float*)d_in[8];
    const float* db3 = (const float*)d_in[9];
    const float* dg  = (const float*)d_in[10];
    const float* dbt = (const float*)d_in[11];
    const float* uW1 = (const float*)d_in[12];
    const float* ub1 = (const float*)d_in[13];
    const float* uW2 = (const float*)d_in[14];
    const float* ub2 = (const float*)d_in[15];
    const float* uW3 = (const float*)d_in[16];
    const float* ub3 = (const float*)d_in[17];
    const float* ug  = (const float*)d_in[18];
    const float* ubt = (const float*)d_in[19];

    int N = in_sizes[0] / C;
    int E = in_sizes[1];
    int n[4];
    n[0] = N;
    for (int i = 0; i < 3; i++) n[i + 1] = (n[i] + 1) / 2;

    void* p;
    float *xs1, *xs2, *xpool, *agg, *feat, *h1, *h2, *xd3, *xu0, *xu1;
    int *permbuf, *nmap, *es, *er, *ecnt, *col, *rowptr, *deg;
    cudaGetSymbolAddress(&p, g_xs1);     xs1 = (float*)p;
    cudaGetSymbolAddress(&p, g_xs2);     xs2 = (float*)p;
    cudaGetSymbolAddress(&p, g_xpool);   xpool = (float*)p;
    cudaGetSymbolAddress(&p, g_agg);     agg = (float*)p;
    cudaGetSymbolAddress(&p, g_feat);    feat = (float*)p;
    cudaGetSymbolAddress(&p, g_h1);      h1 = (float*)p;
    cudaGetSymbolAddress(&p, g_h2);      h2 = (float*)p;
    cudaGetSymbolAddress(&p, g_xd3);     xd3 = (float*)p;
    cudaGetSymbolAddress(&p, g_xu0);     xu0 = (float*)p;
    cudaGetSymbolAddress(&p, g_xu1);     xu1 = (float*)p;
    cudaGetSymbolAddress(&p, g_permbuf); permbuf = (int*)p;
    cudaGetSymbolAddress(&p, g_nmap);    nmap = (int*)p;
    cudaGetSymbolAddress(&p, g_es);      es = (int*)p;
    cudaGetSymbolAddress(&p, g_er);      er = (int*)p;
    cudaGetSymbolAddress(&p, g_ecnt);    ecnt = (int*)p;
    cudaGetSymbolAddress(&p, g_col);     col = (int*)p;
    cudaGetSymbolAddress(&p, g_rowptr);  rowptr = (int*)p;
    cudaGetSymbolAddress(&p, g_deg);     deg = (int*)p;

    int egrid = divup(E, TPB);

    auto build_csr = [&](int set, const int* s, const int* r, int cntConst,
                         const int* cntDev, int nn) {
        int* rp = rowptr + set * (MAXN + 2);
        int* cl = col + (size_t)set * 2 * MAXE;
        k_seti<<<divup(nn + 1, TPB), TPB>>>(deg, nn + 1, 0);
        k_hist<<<egrid, TPB>>>(s, r, cntConst, cntDev);
        k_scan<<<1, 1024>>>(nn, rp);
        k_fill<<<egrid, TPB>>>(s, r, cntConst, cntDev, cl);
    };

    int poff[3] = {0, n[1], n[1] + n[2]};

    build_csr(0, s0, r0, E, nullptr, N);

    // -------------------------------------------------- down path
    const float* xin = x0;
    float* xsbuf[3] = {xs1, xs2, xd3};
    for (int i = 0; i < 3; i++) {
        int nn = n[i], kk = n[i + 1];
        int P = 1;
        while (P < nn) P <<= 1;

        k_score<<<divup(nn, 8), TPB>>>(xin, pw + i * C, nn);
        k_keyinit<<<divup(P, TPB), TPB>>>(nn, P);
        k_sort_local_full<<<P / SCHUNK, 1024>>>();
        for (int k2 = SCHUNK * 2; k2 <= P; k2 <<= 1) {
            for (int j = k2 >> 1; j >= SCHUNK; j >>= 1)
                k_sort_global<<<divup(P / 2, TPB), TPB>>>(j, k2, P);
            k_sort_local_merge<<<P / SCHUNK, 1024>>>(k2);
        }

        int* perm = permbuf + poff[i];
        k_pool<<<divup(kk, 8), TPB>>>(xin, perm, xpool, kk);

        k_seti<<<divup(nn + 1, TPB), TPB>>>(nmap, nn + 1, kk);
        k_nmap_scatter<<<divup(kk, TPB), TPB>>>(perm, kk);
        k_seti<<<1, 32>>>(ecnt + i, 1, 0);
        const int* sin = (i == 0) ? s0 : (es + (i - 1) * MAXE);
        const int* rin = (i == 0) ? r0 : (er + (i - 1) * MAXE);
        const int* cd  = (i == 0) ? nullptr : (ecnt + (i - 1));
        k_remap<<<egrid, TPB>>>(sin, rin, (i == 0) ? E : 0, cd, kk,
                                es + i * MAXE, er + i * MAXE, ecnt + i);

        build_csr(i + 1, es + i * MAXE, er + i * MAXE, 0, ecnt + i, kk);

        k_agg<128><<<divup(kk, 8), TPB>>>(rowptr + (i + 1) * (MAXN + 2),
                                          col + (size_t)(i + 1) * 2 * MAXE, xpool, agg, kk);
        k_gemm<1><<<divup(kk, 128), 256>>>(agg, dW1 + i * C * C, db1 + i * C, h1, kk, C);
        k_gemm<1><<<divup(kk, 128), 256>>>(h1, dW2 + i * C * C, db2 + i * C, h2, kk, C);
        k_gemm<0><<<divup(kk, 128), 256>>>(h2, dW3 + i * C * C, db3 + i * C, h1, kk, C);
        k_ln<<<divup(kk, 8), TPB>>>(h1, dg + i * C, dbt + i * C, xsbuf[i], kk);

        xin = xsbuf[i];
    }

    // -------------------------------------------------- up path
    const float* xcur = xd3;
    for (int i = 0; i < 3; i++) {
        int j = 2 - i;
        int nn = n[j];
        int kk = n[j + 1];
        const float* res = (j == 0) ? x0 : ((j == 1) ? xs1 : xs2);
        const int* perm = permbuf + poff[j];

        k_featcopy<<<divup(nn, 8), TPB>>>(res, nn);
        k_featscatter<<<divup(kk, 8), TPB>>>(perm, xcur, kk);

        k_agg<256><<<divup(nn, 8), TPB>>>(rowptr + j * (MAXN + 2),
                                          col + (size_t)j * 2 * MAXE, feat, agg, nn);
        k_gemm<1><<<divup(nn, 128), 256>>>(agg, uW1 + i * C2 * C, ub1 + i * C, h1, nn, C2);
        k_gemm<1><<<divup(nn, 128), 256>>>(h1, uW2 + i * C * C, ub2 + i * C, h2, nn, C);
        k_gemm<0><<<divup(nn, 128), 256>>>(h2, uW3 + i * C * C, ub3 + i * C, h1, nn, C);

        float* outp = (i == 2) ? (float*)d_out : ((i == 0) ? xu0 : xu1);
        k_ln<<<divup(nn, 8), TPB>>>(h1, ug + i * C, ubt + i * C, outp, nn);
        xcur = outp;
    }
}

// round 16
// speedup vs baseline: 1.1217x; 1.0365x over previous
#include <cuda_runtime.h>
#include <math.h>

#define C    128
#define C2   256
#define MAXN 50000
#define MAXE 600000
#define PADMAX 65536
#define SCHUNK 2048
#define TPB  256

// ------------------------------------------------------------------ scratch
__device__ float g_score[MAXN];
__device__ unsigned long long g_keys[PADMAX];
__device__ float g_xs1[25088 * C];
__device__ float g_xs2[12544 * C];
__device__ float g_xpool[25088 * C];
__device__ float g_agg[MAXN * C2];
__device__ float g_h1[MAXN * C];
__device__ float g_h2[MAXN * C];
__device__ float g_xd3[6272 * C];
__device__ float g_xu0[12544 * C];
__device__ float g_xu1[25088 * C];
__device__ int g_nmaps[3 * (MAXN + 1)];      // per-level node maps (kept for up path)
__device__ int g_es[3 * MAXE];
__device__ int g_er[3 * MAXE];
__device__ int g_ecnt[4];
__device__ int g_col[4 * 2 * MAXE];
__device__ int g_rowptr[4 * (MAXN + 2)];
__device__ int g_deg[MAXN + 1];
__device__ int g_cursor[MAXN + 1];
__device__ float g_zerorow[C];               // stays zero

// ------------------------------------------------------------------ helpers
__device__ __forceinline__ float warp_sum(float v) {
    #pragma unroll
    for (int o = 16; o; o >>= 1) v += __shfl_xor_sync(0xffffffffu, v, o);
    return v;
}

__device__ __forceinline__ float gelu_exact(float v) {
    return 0.5f * v * (1.0f + erff(v * 0.70710678118654752f));
}

__device__ __forceinline__ void ffma2(unsigned long long& d,
                                      unsigned long long a,
                                      unsigned long long b) {
    asm("fma.rn.f32x2 %0, %1, %2, %0;" : "+l"(d) : "l"(a), "l"(b));
}

// ------------------------------------------------------------------ scoring (+key encode)
__global__ void k_score_key(const float* __restrict__ x, const float* __restrict__ w, int nn) {
    int wid  = (blockIdx.x * blockDim.x + threadIdx.x) >> 5;
    int lane = threadIdx.x & 31;
    if (wid >= nn) return;
    float4 wv = *(const float4*)(w + lane * 4);
    float4 xv = *(const float4*)(x + (size_t)wid * C + lane * 4);
    float dot = xv.x * wv.x + xv.y * wv.y + xv.z * wv.z + xv.w * wv.w;
    float nrm = wv.x * wv.x + wv.y * wv.y + wv.z * wv.z + wv.w * wv.w;
    dot = warp_sum(dot);
    nrm = warp_sum(nrm);
    if (lane == 0) {
        float sc = tanhf(dot / sqrtf(nrm));
        g_score[wid] = sc;
        unsigned u = __float_as_uint(sc);
        u = (u & 0x80000000u) ? ~u : (u | 0x80000000u);
        g_keys[wid] = (((unsigned long long)(~u)) << 32) | (unsigned)wid;
    }
}

// prep: pad keys, default nmap, zero deg, zero ecnt
__global__ void k_prep(int nn, int P, int kk, int lvl, int* __restrict__ nmapL) {
    int i = blockIdx.x * blockDim.x + threadIdx.x;
    if (i < P - nn) g_keys[nn + i] = 0xFFFFFFFFFFFFFFFFULL;
    if (i <= nn) { nmapL[i] = kk; g_deg[i] = 0; }
    if (i == 0) g_ecnt[lvl] = 0;
}

// ------------------------------------------------------------------ bitonic sort
__global__ void k_sort_local_full() {
    __shared__ unsigned long long sk[SCHUNK];
    int base = blockIdx.x * SCHUNK;
    int t = threadIdx.x;
    sk[t] = g_keys[base + t];
    sk[t + 1024] = g_keys[base + t + 1024];
    __syncthreads();
    for (int k = 2; k <= SCHUNK; k <<= 1) {
        for (int j = k >> 1; j > 0; j >>= 1) {
            int i = ((t & ~(j - 1)) << 1) | (t & (j - 1));
            int l = i | j;
            bool up = (((base + i) & k) == 0);
            unsigned long long a = sk[i], b = sk[l];
            if ((a > b) == up) { sk[i] = b; sk[l] = a; }
            __syncthreads();
        }
    }
    g_keys[base + t] = sk[t];
    g_keys[base + t + 1024] = sk[t + 1024];
}

// stride-32 slice kernel: handles all j from k2/2 down to 32 in smem.
// block b owns indices { b + 32*q : q in [0, NS) }, NS = P/32.
__global__ void k_sort_strided(int k2, int NS) {
    __shared__ unsigned long long sk[2048];
    int r = blockIdx.x;
    int t = threadIdx.x;                 // NS/2 threads
    int h = NS >> 1;
    sk[t]     = g_keys[r + 32 * t];
    sk[t + h] = g_keys[r + 32 * (t + h)];
    __syncthreads();
    int kq = k2 >> 5;
    for (int jq = kq >> 1; jq >= 1; jq >>= 1) {
        int i = ((t & ~(jq - 1)) << 1) | (t & (jq - 1));
        int l = i | jq;
        bool up = ((i & kq) == 0);
        unsigned long long a = sk[i], b = sk[l];
        if ((a > b) == up) { sk[i] = b; sk[l] = a; }
        __syncthreads();
    }
    g_keys[r + 32 * t]       = sk[t];
    g_keys[r + 32 * (t + h)] = sk[t + h];
}

// tail: j = 16..1 on contiguous 2048 chunks
__global__ void k_sort_tail(int k2) {
    __shared__ unsigned long long sk[SCHUNK];
    int base = blockIdx.x * SCHUNK;
    int t = threadIdx.x;
    sk[t] = g_keys[base + t];
    sk[t + 1024] = g_keys[base + t + 1024];
    __syncthreads();
    bool up = ((base & k2) == 0);
    for (int j = 16; j >= 1; j >>= 1) {
        int i = ((t & ~(j - 1)) << 1) | (t & (j - 1));
        int l = i | j;
        unsigned long long a = sk[i], b = sk[l];
        if ((a > b) == up) { sk[i] = b; sk[l] = a; }
        __syncthreads();
    }
    g_keys[base + t] = sk[t];
    g_keys[base + t + 1024] = sk[t + 1024];
}

// ------------------------------------------------------------------ pooling (+nmap scatter)
__global__ void k_pool(const float* __restrict__ xin, int* __restrict__ nmapL,
                       float* __restrict__ xout, int kk) {
    int wid  = (blockIdx.x * blockDim.x + threadIdx.x) >> 5;
    int lane = threadIdx.x & 31;
    if (wid >= kk) return;
    int p = (int)(g_keys[wid] & 0xFFFFFFFFULL);
    float val = g_score[p];
    if (lane == 0) nmapL[p] = wid;
    float4 v = *(const float4*)(xin + (size_t)p * C + lane * 4);
    v.x *= val; v.y *= val; v.z *= val; v.w *= val;
    *(float4*)(xout + (size_t)wid * C + lane * 4) = v;
}

__global__ void k_seti(int* ptr, int cnt, int val) {
    int i = blockIdx.x * blockDim.x + threadIdx.x;
    if (i < cnt) ptr[i] = val;
}

// warp-aggregated stream compaction + degree histogram
__global__ void k_remap_hist(const int* __restrict__ sin, const int* __restrict__ rin,
                             int cntConst, const int* cntDev, int kk,
                             const int* __restrict__ nmapL,
                             int* __restrict__ sout, int* __restrict__ rout, int* cntOut) {
    int e = blockIdx.x * blockDim.x + threadIdx.x;
    int cnt = cntDev ? __ldg(cntDev) : cntConst;
    bool valid = false;
    int ns = 0, nr = 0;
    if (e < cnt) {
        ns = nmapL[sin[e]];
        nr = nmapL[rin[e]];
        valid = (ns < kk) && (nr < kk);
    }
    unsigned mask = __ballot_sync(0xffffffffu, valid);
    if (!valid) return;
    int lane = threadIdx.x & 31;
    int leader = __ffs(mask) - 1;
    int rank = __popc(mask & ((1u << lane) - 1));
    int base = 0;
    if (lane == leader) base = atomicAdd(cntOut, __popc(mask));
    base = __shfl_sync(mask, base, leader);
    sout[base + rank] = ns;
    rout[base + rank] = nr;
    atomicAdd(&g_deg[nr], 1);
    atomicAdd(&g_deg[ns], 1);
}

// ------------------------------------------------------------------ CSR build
__global__ void k_hist(const int* __restrict__ s, const int* __restrict__ r, int cnt) {
    int e = blockIdx.x * blockDim.x + threadIdx.x;
    if (e >= cnt) return;
    atomicAdd(&g_deg[r[e]], 1);
    atomicAdd(&g_deg[s[e]], 1);
}

__global__ void k_scan(int nn, int* __restrict__ rowptr) {
    __shared__ int warpsum[32];
    __shared__ int carry;
    int t = threadIdx.x, lane = t & 31, wid = t >> 5;
    if (t == 0) { rowptr[0] = 0; carry = 0; }
    __syncthreads();
    for (int base = 0; base < nn; base += 1024) {
        int v = (base + t < nn) ? g_deg[base + t] : 0;
        int x = v;
        #pragma unroll
        for (int o = 1; o < 32; o <<= 1) {
            int y = __shfl_up_sync(0xffffffffu, x, o);
            if (lane >= o) x += y;
        }
        if (lane == 31) warpsum[wid] = x;
        __syncthreads();
        if (wid == 0) {
            int s = warpsum[lane];
            #pragma unroll
            for (int o = 1; o < 32; o <<= 1) {
                int y = __shfl_up_sync(0xffffffffu, s, o);
                if (lane >= o) s += y;
            }
            warpsum[lane] = s;
        }
        __syncthreads();
        int off = carry + (wid ? warpsum[wid - 1] : 0);
        if (base + t < nn) rowptr[base + t + 1] = off + x;
        int total = warpsum[31];
        __syncthreads();
        if (t == 0) carry += total;
        __syncthreads();
    }
    for (int i = t; i <= nn; i += 1024) g_cursor[i] = rowptr[i];
}

__global__ void k_fill(const int* __restrict__ s, const int* __restrict__ r,
                       int cntConst, const int* cntDev, int* __restrict__ col) {
    int e = blockIdx.x * blockDim.x + threadIdx.x;
    int cnt = cntDev ? __ldg(cntDev) : cntConst;
    if (e >= cnt) return;
    int se = s[e], re = r[e];
    int p1 = atomicAdd(&g_cursor[re], 1); col[p1] = se;
    int p2 = atomicAdd(&g_cursor[se], 1); col[p2] = re;
}

// ------------------------------------------------------------------ aggregation (down, CH=128)
__global__ void k_agg(const int* __restrict__ rowptr, const int* __restrict__ colv,
                      const float* __restrict__ x, float* __restrict__ out, int nn) {
    int w    = (blockIdx.x * blockDim.x + threadIdx.x) >> 5;
    int lane = threadIdx.x & 31;
    if (w >= nn) return;
    int beg = rowptr[w], end = rowptr[w + 1];
    float acc[4] = {0.f, 0.f, 0.f, 0.f};
    for (int e = beg; e < end; e++) {
        int u = __ldg(colv + e);
        float4 v = __ldg((const float4*)(x + (size_t)u * C + lane * 4));
        acc[0] += v.x; acc[1] += v.y; acc[2] += v.z; acc[3] += v.w;
    }
    *(float4*)(out + (size_t)w * C + lane * 4) =
        make_float4(acc[0], acc[1], acc[2], acc[3]);
}

// aggregation (up, CH=256): virtual feature row [res[u] | up[u]] gathered on the fly
__global__ void k_agg_up(const int* __restrict__ rowptr, const int* __restrict__ colv,
                         const float* __restrict__ res, const float* __restrict__ xc,
                         const int* __restrict__ nmapL, int kk,
                         float* __restrict__ out, int nn) {
    int w    = (blockIdx.x * blockDim.x + threadIdx.x) >> 5;
    int lane = threadIdx.x & 31;
    if (w >= nn) return;
    int beg = rowptr[w], end = rowptr[w + 1];
    int half = lane >> 4;        // 0: res half, 1: up half
    int sub  = lane & 15;        // 8 floats each
    float acc[8];
    #pragma unroll
    for (int i = 0; i < 8; i++) acc[i] = 0.f;
    for (int e = beg; e < end; e++) {
        int u = __ldg(colv + e);
        const float* bp;
        if (half) {
            int m = __ldg(nmapL + u);
            bp = (m < kk) ? (xc + (size_t)m * C) : g_zerorow;
        } else {
            bp = res + (size_t)u * C;
        }
        const float4* p = (const float4*)(bp + sub * 8);
        float4 v0 = __ldg(p);
        float4 v1 = __ldg(p + 1);
        acc[0] += v0.x; acc[1] += v0.y; acc[2] += v0.z; acc[3] += v0.w;
        acc[4] += v1.x; acc[5] += v1.y; acc[6] += v1.z; acc[7] += v1.w;
    }
    float4* o = (float4*)(out + (size_t)w * C2 + lane * 8);
    o[0] = make_float4(acc[0], acc[1], acc[2], acc[3]);
    o[1] = make_float4(acc[4], acc[5], acc[6], acc[7]);
}

// ------------------------------------------------------------------ GEMM (M x K @ K x 128 + bias [+gelu] [+LayerNorm])
// f32x2 packed FMA, 128x128 tile, KT=16, double-buffered smem.
template <int ACT, int LN>
__global__ __launch_bounds__(256, 2) void k_gemm(const float* __restrict__ A,
                                                 const float* __restrict__ W,
                                                 const float* __restrict__ bias,
                                                 const float* __restrict__ gamma,
                                                 const float* __restrict__ beta,
                                                 float* __restrict__ out, int M, int K) {
    __shared__ float As[2][16][128];        // [buf][kk][m]
    __shared__ float Bs[2][16][4][64];      // [buf][kk][q][tx*4+e]  (duplicated pairs)
    const int tid = threadIdx.x;
    const int row0 = blockIdx.x * 128;
    const int tx = tid & 15, ty = tid >> 4;

    const int ar = tid >> 1;
    const int ac = (tid & 1) * 8;
    const int wr = tid >> 5;
    const int wc = (tid & 31) * 4;
    const int wtx = wc >> 3;
    const int wq = (wc & 7) >> 1;

    const int nt = K >> 4;
    const int arow = row0 + ar;
    const bool aval = (arow < M);
    const float* Aptr = A + (size_t)(aval ? arow : 0) * K + ac;

    unsigned long long acc[4][8];
    #pragma unroll
    for (int p = 0; p < 4; p++)
        #pragma unroll
        for (int j = 0; j < 8; j++) acc[p][j] = 0ULL;

    float4 a0, a1, w0, w1;
    if (aval) { a0 = *(const float4*)(Aptr); a1 = *(const float4*)(Aptr + 4); }
    else { a0 = make_float4(0.f, 0.f, 0.f, 0.f); a1 = a0; }
    w0 = *(const float4*)(W + (size_t)wr * 128 + wc);
    w1 = *(const float4*)(W + (size_t)(wr + 8) * 128 + wc);

    As[0][ac + 0][ar] = a0.x; As[0][ac + 1][ar] = a0.y;
    As[0][ac + 2][ar] = a0.z; As[0][ac + 3][ar] = a0.w;
    As[0][ac + 4][ar] = a1.x; As[0][ac + 5][ar] = a1.y;
    As[0][ac + 6][ar] = a1.z; As[0][ac + 7][ar] = a1.w;
    *(float4*)&Bs[0][wr][wq][wtx * 4]         = make_float4(w0.x, w0.x, w0.y, w0.y);
    *(float4*)&Bs[0][wr][wq + 1][wtx * 4]     = make_float4(w0.z, w0.z, w0.w, w0.w);
    *(float4*)&Bs[0][wr + 8][wq][wtx * 4]     = make_float4(w1.x, w1.x, w1.y, w1.y);
    *(float4*)&Bs[0][wr + 8][wq + 1][wtx * 4] = make_float4(w1.z, w1.z, w1.w, w1.w);
    __syncthreads();

    for (int t = 0; t < nt; t++) {
        const int cur = t & 1;
        if (t + 1 < nt) {
            int k0 = (t + 1) * 16;
            if (aval) { a0 = *(const float4*)(Aptr + k0); a1 = *(const float4*)(Aptr + k0 + 4); }
            w0 = *(const float4*)(W + (size_t)(k0 + wr) * 128 + wc);
            w1 = *(const float4*)(W + (size_t)(k0 + wr + 8) * 128 + wc);
        }
        #pragma unroll
        for (int kk = 0; kk < 16; kk++) {
            ulonglong2 av0 = *(const ulonglong2*)&As[cur][kk][ty * 8];
            ulonglong2 av1 = *(const ulonglong2*)&As[cur][kk][ty * 8 + 4];
            unsigned long long a2[4] = {av0.x, av0.y, av1.x, av1.y};
            unsigned long long b2[8];
            #pragma unroll
            for (int q = 0; q < 4; q++) {
                ulonglong2 bv = *(const ulonglong2*)&Bs[cur][kk][q][tx * 4];
                b2[2 * q] = bv.x;
                b2[2 * q + 1] = bv.y;
            }
            #pragma unroll
            for (int p = 0; p < 4; p++)
                #pragma unroll
                for (int j = 0; j < 8; j++) ffma2(acc[p][j], a2[p], b2[j]);
        }
        if (t + 1 < nt) {
            const int nb = 1 - cur;
            As[nb][ac + 0][ar] = a0.x; As[nb][ac + 1][ar] = a0.y;
            As[nb][ac + 2][ar] = a0.z; As[nb][ac + 3][ar] = a0.w;
            As[nb][ac + 4][ar] = a1.x; As[nb][ac + 5][ar] = a1.y;
            As[nb][ac + 6][ar] = a1.z; As[nb][ac + 7][ar] = a1.w;
            *(float4*)&Bs[nb][wr][wq][wtx * 4]         = make_float4(w0.x, w0.x, w0.y, w0.y);
            *(float4*)&Bs[nb][wr][wq + 1][wtx * 4]     = make_float4(w0.z, w0.z, w0.w, w0.w);
            *(float4*)&Bs[nb][wr + 8][wq][wtx * 4]     = make_float4(w1.x, w1.x, w1.y, w1.y);
            *(float4*)&Bs[nb][wr + 8][wq + 1][wtx * 4] = make_float4(w1.z, w1.z, w1.w, w1.w);
            __syncthreads();
        }
    }

    float bvv[8];
    *(float4*)&bvv[0] = *(const float4*)(bias + tx * 8);
    *(float4*)&bvv[4] = *(const float4*)(bias + tx * 8 + 4);
    float gv[8], btv[8];
    if (LN) {
        *(float4*)&gv[0]  = *(const float4*)(gamma + tx * 8);
        *(float4*)&gv[4]  = *(const float4*)(gamma + tx * 8 + 4);
        *(float4*)&btv[0] = *(const float4*)(beta + tx * 8);
        *(float4*)&btv[4] = *(const float4*)(beta + tx * 8 + 4);
    }
    #pragma unroll
    for (int p = 0; p < 4; p++) {
        int r0 = row0 + ty * 8 + 2 * p;
        float o0[8], o1[8];
        #pragma unroll
        for (int j = 0; j < 8; j++) {
            float2 u = *(float2*)&acc[p][j];
            float v0 = u.x + bvv[j];
            float v1 = u.y + bvv[j];
            if (ACT) { v0 = gelu_exact(v0); v1 = gelu_exact(v1); }
            o0[j] = v0; o1[j] = v1;
        }
        if (LN) {
            float s0 = 0.f, s1 = 0.f;
            #pragma unroll
            for (int j = 0; j < 8; j++) { s0 += o0[j]; s1 += o1[j]; }
            #pragma unroll
            for (int o = 1; o < 16; o <<= 1) {
                s0 += __shfl_xor_sync(0xffffffffu, s0, o);
                s1 += __shfl_xor_sync(0xffffffffu, s1, o);
            }
            float mu0 = s0 * (1.0f / 128.0f), mu1 = s1 * (1.0f / 128.0f);
            float q0 = 0.f, q1 = 0.f;
            #pragma unroll
            for (int j = 0; j < 8; j++) {
                float d0 = o0[j] - mu0, d1 = o1[j] - mu1;
                q0 += d0 * d0; q1 += d1 * d1;
            }
            #pragma unroll
            for (int o = 1; o < 16; o <<= 1) {
                q0 += __shfl_xor_sync(0xffffffffu, q0, o);
                q1 += __shfl_xor_sync(0xffffffffu, q1, o);
            }
            float rs0 = rsqrtf(q0 * (1.0f / 128.0f) + 1e-5f);
            float rs1 = rsqrtf(q1 * (1.0f / 128.0f) + 1e-5f);
            #pragma unroll
            for (int j = 0; j < 8; j++) {
                o0[j] = gv[j] * (o0[j] - mu0) * rs0 + btv[j];
                o1[j] = gv[j] * (o1[j] - mu1) * rs1 + btv[j];
            }
        }
        if (r0 < M) {
            *(float4*)(out + (size_t)r0 * 128 + tx * 8)     = *(float4*)&o0[0];
            *(float4*)(out + (size_t)r0 * 128 + tx * 8 + 4) = *(float4*)&o0[4];
        }
        if (r0 + 1 < M) {
            *(float4*)(out + (size_t)(r0 + 1) * 128 + tx * 8)     = *(float4*)&o1[0];
            *(float4*)(out + (size_t)(r0 + 1) * 128 + tx * 8 + 4) = *(float4*)&o1[4];
        }
    }
}

// ------------------------------------------------------------------ host
static inline int divup(int a, int b) { return (a + b - 1) / b; }

extern "C" void kernel_launch(void* const* d_in, const int* in_sizes, int n_in,
                              void* d_out, int out_size) {
    const float* x0  = (const float*)d_in[0];
    const int*   s0  = (const int*)d_in[1];
    const int*   r0  = (const int*)d_in[2];
    const float* pw  = (const float*)d_in[3];
    const float* dW1 = (const float*)d_in[4];
    const float* db1 = (const float*)d_in[5];
    const float* dW2 = (const float*)d_in[6];
    const float* db2 = (const float*)d_in[7];
    const float* dW3 = (const float*)d_in[8];
    const float* db3 = (const float*)d_in[9];
    const float* dg  = (const float*)d_in[10];
    const float* dbt = (const float*)d_in[11];
    const float* uW1 = (const float*)d_in[12];
    const float* ub1 = (const float*)d_in[13];
    const float* uW2 = (const float*)d_in[14];
    const float* ub2 = (const float*)d_in[15];
    const float* uW3 = (const float*)d_in[16];
    const float* ub3 = (const float*)d_in[17];
    const float* ug  = (const float*)d_in[18];
    const float* ubt = (const float*)d_in[19];

    int N = in_sizes[0] / C;
    int E = in_sizes[1];
    int n[4];
    n[0] = N;
    for (int i = 0; i < 3; i++) n[i + 1] = (n[i] + 1) / 2;

    void* p;
    float *xs1, *xs2, *xpool, *agg, *h1, *h2, *xd3, *xu0, *xu1;
    int *nmaps, *es, *er, *ecnt, *col, *rowptr, *deg;
    cudaGetSymbolAddress(&p, g_xs1);    xs1 = (float*)p;
    cudaGetSymbolAddress(&p, g_xs2);    xs2 = (float*)p;
    cudaGetSymbolAddress(&p, g_xpool);  xpool = (float*)p;
    cudaGetSymbolAddress(&p, g_agg);    agg = (float*)p;
    cudaGetSymbolAddress(&p, g_h1);     h1 = (float*)p;
    cudaGetSymbolAddress(&p, g_h2);     h2 = (float*)p;
    cudaGetSymbolAddress(&p, g_xd3);    xd3 = (float*)p;
    cudaGetSymbolAddress(&p, g_xu0);    xu0 = (float*)p;
    cudaGetSymbolAddress(&p, g_xu1);    xu1 = (float*)p;
    cudaGetSymbolAddress(&p, g_nmaps);  nmaps = (int*)p;
    cudaGetSymbolAddress(&p, g_es);     es = (int*)p;
    cudaGetSymbolAddress(&p, g_er);     er = (int*)p;
    cudaGetSymbolAddress(&p, g_ecnt);   ecnt = (int*)p;
    cudaGetSymbolAddress(&p, g_col);    col = (int*)p;
    cudaGetSymbolAddress(&p, g_rowptr); rowptr = (int*)p;
    cudaGetSymbolAddress(&p, g_deg);    deg = (int*)p;

    int egrid = divup(E, TPB);

    // ---------------- initial CSR over original edges (set 0)
    k_seti<<<divup(N + 1, TPB), TPB>>>(deg, N + 1, 0);
    k_hist<<<egrid, TPB>>>(s0, r0, E);
    k_scan<<<1, 1024>>>(N, rowptr);
    k_fill<<<egrid, TPB>>>(s0, r0, E, nullptr, col);

    // -------------------------------------------------- down path
    const float* xin = x0;
    float* xsbuf[3] = {xs1, xs2, xd3};
    for (int i = 0; i < 3; i++) {
        int nn = n[i], kk = n[i + 1];
        int P = 1;
        while (P < nn) P <<= 1;
        int* nmapL = nmaps + i * (MAXN + 1);

        k_score_key<<<divup(nn, 8), TPB>>>(xin, pw + i * C, nn);
        int prepN = (nn + 1 > P - nn) ? nn + 1 : P - nn;
        k_prep<<<divup(prepN, TPB), TPB>>>(nn, P, kk, i, nmapL);

        k_sort_local_full<<<P / SCHUNK, 1024>>>();
        int NS = P / 32;
        for (int k2 = 2 * SCHUNK; k2 <= P; k2 <<= 1) {
            k_sort_strided<<<32, NS / 2>>>(k2, NS);
            k_sort_tail<<<P / SCHUNK, 1024>>>(k2);
        }

        k_pool<<<divup(kk, 8), TPB>>>(xin, nmapL, xpool, kk);

        const int* sin = (i == 0) ? s0 : (es + (i - 1) * MAXE);
        const int* rin = (i == 0) ? r0 : (er + (i - 1) * MAXE);
        const int* cd  = (i == 0) ? nullptr : (ecnt + (i - 1));
        k_remap_hist<<<egrid, TPB>>>(sin, rin, (i == 0) ? E : 0, cd, kk, nmapL,
                                     es + i * MAXE, er + i * MAXE, ecnt + i);

        int* rp = rowptr + (i + 1) * (MAXN + 2);
        int* cl = col + (size_t)(i + 1) * 2 * MAXE;
        k_scan<<<1, 1024>>>(kk, rp);
        k_fill<<<egrid, TPB>>>(es + i * MAXE, er + i * MAXE, 0, ecnt + i, cl);

        k_agg<<<divup(kk, 8), TPB>>>(rp, cl, xpool, agg, kk);
        k_gemm<1,0><<<divup(kk, 128), 256>>>(agg, dW1 + i * C * C, db1 + i * C,
                                             nullptr, nullptr, h1, kk, C);
        k_gemm<1,0><<<divup(kk, 128), 256>>>(h1, dW2 + i * C * C, db2 + i * C,
                                             nullptr, nullptr, h2, kk, C);
        k_gemm<0,1><<<divup(kk, 128), 256>>>(h2, dW3 + i * C * C, db3 + i * C,
                                             dg + i * C, dbt + i * C, xsbuf[i], kk, C);
        xin = xsbuf[i];
    }

    // -------------------------------------------------- up path
    const float* xcur = xd3;
    for (int i = 0; i < 3; i++) {
        int j = 2 - i;
        int nn = n[j];
        int kk = n[j + 1];
        const float* res = (j == 0) ? x0 : ((j == 1) ? xs1 : xs2);
        const int* nmapL = nmaps + j * (MAXN + 1);

        k_agg_up<<<divup(nn, 8), TPB>>>(rowptr + j * (MAXN + 2),
                                        col + (size_t)j * 2 * MAXE,
                                        res, xcur, nmapL, kk, agg, nn);
        k_gemm<1,0><<<divup(nn, 128), 256>>>(agg, uW1 + i * C2 * C, ub1 + i * C,
                                             nullptr, nullptr, h1, nn, C2);
        k_gemm<1,0><<<divup(nn, 128), 256>>>(h1, uW2 + i * C * C, ub2 + i * C,
                                             nullptr, nullptr, h2, nn, C);
        float* outp = (i == 2) ? (float*)d_out : ((i == 0) ? xu0 : xu1);
        k_gemm<0,1><<<divup(nn, 128), 256>>>(h2, uW3 + i * C * C, ub3 + i * C,
                                             ug + i * C, ubt + i * C, outp, nn, C);
        xcur = outp;
    }
}